// round 5
// baseline (speedup 1.0000x reference)
#include <cuda_runtime.h>
#include <cuda_fp16.h>
#include <cstdint>
#include <cstddef>

#define A_   8
#define Bsz  32768
#define EPSB 1e-5f

// ---------------- static scratch ----------------
__device__ float g_part[8 * 32 * 160 * 2];
__device__ float g_mean[8 * 160];
__device__ float g_istd[8 * 160];
// pre-split (hi,lo) fp16 pairs, 1 uint32 per element (value = hi+lo)
__device__ __align__(128) uint32_t g_ci[(size_t)A_ * Bsz * 256];  // [sa_enc | attended]
// plain fp16 tensors for attention
__device__ __align__(128) __half g_keysh[(size_t)A_ * Bsz * 128];
__device__ __align__(128) __half g_selsh[(size_t)A_ * Bsz * 128];
__device__ __align__(128) __half g_valsh[(size_t)A_ * Bsz * 128];
// dup-packed fp16 weights for mainloop GEMMs: [agent][n][K'=2K]
__device__ __align__(128) __half g_Benc [(size_t)8 * 128 * 320];
__device__ __align__(128) __half g_Baenc[(size_t)8 * 128 * 64];
__device__ __align__(128) __half g_Bc1  [(size_t)8 * 128 * 512];
// plain fp16 transposed [n][K=128] for in-kernel second GEMMs
__device__ __align__(128) __half g_Wkp[128 * 128];
__device__ __align__(128) __half g_Wsp[128 * 128];
__device__ __align__(128) __half g_Wvp[128 * 128];

__device__ __forceinline__ float lrelu(float x) { return fmaxf(x, 0.01f * x); }
__device__ __forceinline__ uint32_t smem_u32(const void* p) {
    uint32_t a;
    asm("{ .reg .u64 t; cvta.to.shared.u64 t, %1; cvt.u32.u64 %0, t; }" : "=r"(a) : "l"(p));
    return a;
}
__device__ __forceinline__ void ldsm4(uint32_t* r, uint32_t addr) {
    asm volatile("ldmatrix.sync.aligned.m8n8.x4.shared.b16 {%0,%1,%2,%3}, [%4];"
        : "=r"(r[0]), "=r"(r[1]), "=r"(r[2]), "=r"(r[3]) : "r"(addr));
}
__device__ __forceinline__ void mma16816(float* d, const uint32_t* a, const uint32_t* b) {
    asm volatile("mma.sync.aligned.m16n8k16.row.col.f32.f16.f16.f32 "
        "{%0,%1,%2,%3}, {%4,%5,%6,%7}, {%8,%9}, {%0,%1,%2,%3};"
        : "+f"(d[0]), "+f"(d[1]), "+f"(d[2]), "+f"(d[3])
        : "r"(a[0]), "r"(a[1]), "r"(a[2]), "r"(a[3]), "r"(b[0]), "r"(b[1]));
}
#define CP16(s, g) asm volatile("cp.async.cg.shared.global [%0], [%1], 16;" :: "r"(s), "l"(g))
#define CPCOMMIT() asm volatile("cp.async.commit_group;" ::: "memory")
#define CPWAIT1()  asm volatile("cp.async.wait_group 1;" ::: "memory")
#define CPWAIT0()  asm volatile("cp.async.wait_group 0;" ::: "memory")

__device__ __forceinline__ uint32_t pkh2(__half a, __half b) {
    __half2 h = __halves2half2(a, b);
    return *(uint32_t*)&h;
}
__device__ __forceinline__ uint32_t splitpk(float x) {
    __half h = __float2half_rn(x);
    __half l = __float2half_rn(x - __half2float(h));
    return pkh2(h, l);
}

// ---------------- BatchNorm stats ----------------
__global__ void bn_partial_k(const float* __restrict__ states,
                             const float* __restrict__ actions) {
    int a = blockIdx.y, chunk = blockIdx.x;
    int t = threadIdx.x;
    int f = t % 160, r0 = t / 160;
    size_t sb = (size_t)a * Bsz * 128, ab = (size_t)a * Bsz * 32;
    int row0 = chunk * 1024;
    float s = 0.f, s2 = 0.f;
    if (f < 128) {
        const float* p = states + sb + (size_t)(row0 + r0) * 128 + f;
        #pragma unroll 4
        for (int r = 0; r < 512; r++) { float v = *p; p += 256; s += v; s2 += v * v; }
    } else {
        const float* p = actions + ab + (size_t)(row0 + r0) * 32 + (f - 128);
        #pragma unroll 4
        for (int r = 0; r < 512; r++) { float v = *p; p += 64; s += v; s2 += v * v; }
    }
    __shared__ float sh[640];
    sh[t] = s; sh[320 + t] = s2;
    __syncthreads();
    if (t < 160) {
        float ss = sh[t] + sh[t + 160];
        float qq = sh[320 + t] + sh[320 + t + 160];
        int o = ((a * 32 + chunk) * 160 + t) * 2;
        g_part[o] = ss; g_part[o + 1] = qq;
    }
}

__global__ void bn_final_k() {
    int a = blockIdx.x, f = threadIdx.x;
    float s = 0.f, s2 = 0.f;
    for (int c = 0; c < 32; c++) {
        int o = ((a * 32 + c) * 160 + f) * 2;
        s += g_part[o]; s2 += g_part[o + 1];
    }
    float m = s * (1.f / 32768.f);
    float v = s2 * (1.f / 32768.f) - m * m;
    g_mean[a * 160 + f] = m;
    g_istd[a * 160 + f] = rsqrtf(v + EPSB);
}

// ---------------- weight pack: transpose + fp16 (+dup) ----------------
// mode 0: src [a][k][n=128]    mode 1: heads src [(n>>5)][k][n&31]
__global__ void pack_w(const float* __restrict__ src, __half* __restrict__ dst,
                       int K, int mode, int dup) {
    __shared__ float tile[16][128];
    int a = blockIdx.y, kt = blockIdx.x, t = threadIdx.x;
    int k0 = kt * 16;
    #pragma unroll
    for (int i = 0; i < 2; i++) {
        int p = t + i * 256;
        int kk = p >> 5, n4 = (p & 31) * 4;
        float4 v;
        if (mode == 0)
            v = *(const float4*)(src + ((size_t)a * K + k0 + kk) * 128 + n4);
        else
            v = *(const float4*)(src + ((size_t)(n4 >> 5) * 128 + k0 + kk) * 32 + (n4 & 31));
        tile[kk][n4] = v.x; tile[kk][n4 + 1] = v.y;
        tile[kk][n4 + 2] = v.z; tile[kk][n4 + 3] = v.w;
    }
    __syncthreads();
    #pragma unroll
    for (int i = 0; i < 2; i++) {
        int p = t + i * 256;
        int n = p >> 2, kq = p & 3;
        __half h[4];
        #pragma unroll
        for (int j = 0; j < 4; j++)
            h[j] = __float2half_rn(tile[kq * 4 + j][n]);
        if (dup) {
            int K2 = 2 * K;
            uint4 u;
            u.x = pkh2(h[0], h[0]); u.y = pkh2(h[1], h[1]);
            u.z = pkh2(h[2], h[2]); u.w = pkh2(h[3], h[3]);
            *(uint4*)(dst + (size_t)a * 128 * K2 + (size_t)n * K2 + kt * 32 + kq * 8) = u;
        } else {
            uint2 u;
            u.x = pkh2(h[0], h[1]); u.y = pkh2(h[2], h[3]);
            *(uint2*)(dst + (size_t)a * 128 * K + (size_t)n * K + kt * 16 + kq * 4) = u;
        }
    }
}

// ---------------- fused GEMM chain ----------------
// Main GEMM: C = lrelu(A @ Bdup + bias), A from BN generators or pre-split pairs.
// MOUT: 0 -> tile-only (smem), 1 -> ci pairs + tile, 2 -> q output (c1+c2 fusion)
// NB2:  number of resident second-GEMM weights (0,1,2). Second GEMM: tile(fp16) @ W2 -> fp16 out.
#define PITCH 80
#define STAGE 20480
#define CHNK  10240

template<int SRC, int MOUT, int NB2>
__global__ __launch_bounds__(256, 1) void gemm_fused(
    const uint32_t* __restrict__ Apairs, int lda,
    const float* __restrict__ states, const float* __restrict__ actions,
    const __half* __restrict__ Bt, long wstride,
    const float* __restrict__ bias, int bstride,
    uint32_t* __restrict__ Cpairs, int ldc,
    const __half* __restrict__ B2a, const __half* __restrict__ B2b,
    const float* __restrict__ bias2b,
    __half* __restrict__ Out2a, __half* __restrict__ Out2b,
    const float* __restrict__ c2w, const float* __restrict__ c2b,
    float* __restrict__ qout,
    int Kdim) {

    extern __shared__ __align__(16) char sm[];
    constexpr uint32_t B2AOFF = 40960;
    constexpr uint32_t B2BOFF = 81920;
    constexpr uint32_t TILEOFF = 40960 + NB2 * 40960;

    int tid = threadIdx.x, lane = tid & 31, wid = tid >> 5;
    int wm = wid & 3, wn = wid >> 2;
    int a = blockIdx.z, m0 = blockIdx.x * 128;
    int K2 = Kdim * 2;
    int nch = Kdim >> 4;

    const float* mp = g_mean + a * 160;
    const float* ip = g_istd + a * 160;
    size_t sbo = (size_t)a * Bsz * 128, abo = (size_t)a * Bsz * 32;
    const uint32_t* Ap = (SRC == 0) ? (Apairs + (size_t)a * Bsz * lda) : nullptr;
    const __half* Bp = Bt + (size_t)a * wstride;

    uint32_t smu = smem_u32(sm);

    // resident second-GEMM weights via cp.async (own group, drains with mainloop waits)
    if (NB2 >= 1) {
        #pragma unroll
        for (int i = 0; i < 8; i++) {
            int s = tid + 256 * i;                    // 0..2047
            int n = s >> 4, sr = s & 15;
            uint32_t dst = smu + B2AOFF + (sr >> 2) * CHNK + n * PITCH + (sr & 3) * 16;
            CP16(dst, B2a + (size_t)n * 128 + sr * 8);
        }
        if (NB2 == 2) {
            #pragma unroll
            for (int i = 0; i < 8; i++) {
                int s = tid + 256 * i;
                int n = s >> 4, sr = s & 15;
                uint32_t dst = smu + B2BOFF + (sr >> 2) * CHNK + n * PITCH + (sr & 3) * 16;
                CP16(dst, B2b + (size_t)n * 128 + sr * 8);
            }
        }
        CPCOMMIT();
    }

    float4 av[2];
    auto loadA = [&](int c) {
        #pragma unroll
        for (int i = 0; i < 2; i++) {
            int p = tid + i * 256;
            int row = p >> 2, kq = p & 3;
            int k = c * 16 + kq * 4;
            float4 v;
            if (SRC == 1) {
                if (k < 128) v = *(const float4*)(states + sbo + (size_t)(m0 + row) * 128 + k);
                else         v = *(const float4*)(actions + abo + (size_t)(m0 + row) * 32 + (k - 128));
                v.x = (v.x - mp[k    ]) * ip[k    ];
                v.y = (v.y - mp[k + 1]) * ip[k + 1];
                v.z = (v.z - mp[k + 2]) * ip[k + 2];
                v.w = (v.w - mp[k + 3]) * ip[k + 3];
            } else {
                v = *(const float4*)(actions + abo + (size_t)(m0 + row) * 32 + k);
                v.x = (v.x - mp[128 + k]) * ip[128 + k];
                v.y = (v.y - mp[129 + k]) * ip[129 + k];
                v.z = (v.z - mp[130 + k]) * ip[130 + k];
                v.w = (v.w - mp[131 + k]) * ip[131 + k];
            }
            av[i] = v;
        }
    };
    auto stsA = [&](int buf) {
        #pragma unroll
        for (int i = 0; i < 2; i++) {
            int p = tid + i * 256;
            int row = p >> 2, kq = p & 3;
            float4 v = av[i];
            uint4 u;
            u.x = splitpk(v.x); u.y = splitpk(v.y);
            u.z = splitpk(v.z); u.w = splitpk(v.w);
            *(uint4*)(sm + buf * STAGE + row * PITCH + kq * 16) = u;
        }
    };
    auto cpA = [&](int c, int buf) {
        #pragma unroll
        for (int i = 0; i < 2; i++) {
            int p = tid + i * 256;
            int row = p >> 2, seg = p & 3;
            const uint32_t* g = Ap + (size_t)(m0 + row) * lda + c * 16 + seg * 4;
            CP16(smu + buf * STAGE + row * PITCH + seg * 16, g);
        }
    };
    auto cpB = [&](int c, int buf) {
        #pragma unroll
        for (int i = 0; i < 2; i++) {
            int s = tid + i * 256;
            int n = s >> 2, seg = s & 3;
            const __half* g = Bp + (size_t)n * K2 + c * 32 + seg * 8;
            CP16(smu + buf * STAGE + 10240 + n * PITCH + seg * 16, g);
        }
    };

    int r = lane & 7, q = lane >> 3;
    uint32_t a_off[2], b_off[4], b2_off[4];
    #pragma unroll
    for (int mt = 0; mt < 2; mt++)
        a_off[mt] = (uint32_t)((wm * 32 + mt * 16 + (q & 1) * 8 + r) * PITCH + (q >> 1) * 16);
    #pragma unroll
    for (int np = 0; np < 4; np++) {
        b_off[np]  = (uint32_t)(10240 + (wn * 64 + np * 16 + (q >> 1) * 8 + r) * PITCH + (q & 1) * 16);
        b2_off[np] = (uint32_t)((wn * 64 + np * 16 + (q >> 1) * 8 + r) * PITCH + (q & 1) * 16);
    }

    float acc[2][8][4];
    #pragma unroll
    for (int mt = 0; mt < 2; mt++)
        #pragma unroll
        for (int nt = 0; nt < 8; nt++)
            #pragma unroll
            for (int i = 0; i < 4; i++) acc[mt][nt][i] = 0.f;

    if (SRC == 0) { cpA(0, 0); cpB(0, 0); CPCOMMIT(); }
    else          { loadA(0);  cpB(0, 0); CPCOMMIT(); }

    for (int c = 0; c < nch; c++) {
        int buf = c & 1;
        if (SRC == 0) {
            if (c + 1 < nch) { cpA(c + 1, buf ^ 1); cpB(c + 1, buf ^ 1); CPCOMMIT(); CPWAIT1(); }
            else             { CPWAIT0(); }
        } else {
            if (c + 1 < nch) { cpB(c + 1, buf ^ 1); CPCOMMIT(); }
            stsA(buf);
            if (c + 1 < nch) { loadA(c + 1); CPWAIT1(); }
            else             { CPWAIT0(); }
        }
        __syncthreads();
        uint32_t bb = smu + buf * STAGE;
        #pragma unroll
        for (int ks = 0; ks < 2; ks++) {
            uint32_t af[2][4], bf[4][4];
            #pragma unroll
            for (int mt = 0; mt < 2; mt++) ldsm4(af[mt], bb + a_off[mt] + ks * 32);
            #pragma unroll
            for (int np = 0; np < 4; np++) ldsm4(bf[np], bb + b_off[np] + ks * 32);
            #pragma unroll
            for (int mt = 0; mt < 2; mt++)
                #pragma unroll
                for (int nt = 0; nt < 8; nt++)
                    mma16816(acc[mt][nt], af[mt], &bf[nt >> 1][(nt & 1) * 2]);
        }
        __syncthreads();
    }

    int g = lane >> 2, tig = lane & 3;

    // ---- epilogue stage 1: bias + lrelu, route to ci/tile/q ----
    if (MOUT == 2) {
        float qp[4] = {0.f, 0.f, 0.f, 0.f};
        #pragma unroll
        for (int mt = 0; mt < 2; mt++)
            #pragma unroll
            for (int nt = 0; nt < 8; nt++) {
                int col = wn * 64 + nt * 8 + 2 * tig;
                float b0 = bias[a * bstride + col], b1 = bias[a * bstride + col + 1];
                float w0 = c2w[a * 128 + col], w1 = c2w[a * 128 + col + 1];
                qp[mt * 2]     += lrelu(acc[mt][nt][0] + b0) * w0 + lrelu(acc[mt][nt][1] + b1) * w1;
                qp[mt * 2 + 1] += lrelu(acc[mt][nt][2] + b0) * w0 + lrelu(acc[mt][nt][3] + b1) * w1;
            }
        #pragma unroll
        for (int j = 0; j < 4; j++) {
            qp[j] += __shfl_xor_sync(0xffffffffu, qp[j], 1);
            qp[j] += __shfl_xor_sync(0xffffffffu, qp[j], 2);
        }
        __syncthreads();
        float* qsm = (float*)sm;
        if (tig == 0) {
            #pragma unroll
            for (int j = 0; j < 4; j++) {
                int rl = wm * 32 + (j >> 1) * 16 + (j & 1) * 8 + g;
                qsm[rl * 2 + wn] = qp[j];
            }
        }
        __syncthreads();
        if (tid < 128)
            qout[(size_t)a * Bsz + m0 + tid] = qsm[tid * 2] + qsm[tid * 2 + 1] + c2b[a];
        return;
    }

    #pragma unroll
    for (int mt = 0; mt < 2; mt++) {
        int row = wm * 32 + mt * 16 + g;
        #pragma unroll
        for (int nt = 0; nt < 8; nt++) {
            int col = wn * 64 + nt * 8 + 2 * tig;
            float b0 = bias[a * bstride + col], b1 = bias[a * bstride + col + 1];
            float v0 = lrelu(acc[mt][nt][0] + b0), v1 = lrelu(acc[mt][nt][1] + b1);
            float v2 = lrelu(acc[mt][nt][2] + b0), v3 = lrelu(acc[mt][nt][3] + b1);
            if (MOUT == 1) {
                uint2 u0; u0.x = splitpk(v0); u0.y = splitpk(v1);
                uint2 u1; u1.x = splitpk(v2); u1.y = splitpk(v3);
                *(uint2*)(Cpairs + ((size_t)a * Bsz + m0 + row) * ldc + col) = u0;
                *(uint2*)(Cpairs + ((size_t)a * Bsz + m0 + row + 8) * ldc + col) = u1;
            }
            uint32_t tadr = TILEOFF + (uint32_t)((col >> 5) * CHNK + row * PITCH + (col & 31) * 2);
            *(__half2*)(sm + tadr)            = __floats2half2_rn(v0, v1);
            *(__half2*)(sm + tadr + 8 * PITCH) = __floats2half2_rn(v2, v3);
        }
    }
    __syncthreads();

    // ---- second GEMM(s): tile(fp16, K=128) @ W2 -> fp16 outputs ----
    if (NB2 >= 1) {
        #pragma unroll
        for (int pass = 0; pass < NB2; pass++) {
            uint32_t b2base = smu + (pass == 0 ? B2AOFF : B2BOFF);
            __half* outp = (pass == 0) ? Out2a : Out2b;
            const float* b2 = (pass == 0) ? nullptr : bias2b;
            float a2[2][8][4];
            #pragma unroll
            for (int mt = 0; mt < 2; mt++)
                #pragma unroll
                for (int nt = 0; nt < 8; nt++)
                    #pragma unroll
                    for (int i = 0; i < 4; i++) a2[mt][nt][i] = 0.f;
            #pragma unroll
            for (int ks2 = 0; ks2 < 8; ks2++) {
                uint32_t coff = (uint32_t)((ks2 >> 1) * CHNK + (ks2 & 1) * 32);
                uint32_t af[2][4], bf[4][4];
                #pragma unroll
                for (int mt = 0; mt < 2; mt++) ldsm4(af[mt], smu + TILEOFF + a_off[mt] + coff);
                #pragma unroll
                for (int np = 0; np < 4; np++) ldsm4(bf[np], b2base + b2_off[np] + coff);
                #pragma unroll
                for (int mt = 0; mt < 2; mt++)
                    #pragma unroll
                    for (int nt = 0; nt < 8; nt++)
                        mma16816(a2[mt][nt], af[mt], &bf[nt >> 1][(nt & 1) * 2]);
            }
            #pragma unroll
            for (int mt = 0; mt < 2; mt++) {
                int m = m0 + wm * 32 + mt * 16 + g;
                #pragma unroll
                for (int nt = 0; nt < 8; nt++) {
                    int col = wn * 64 + nt * 8 + 2 * tig;
                    float v0 = a2[mt][nt][0], v1 = a2[mt][nt][1];
                    float v2 = a2[mt][nt][2], v3 = a2[mt][nt][3];
                    if (pass == 1) {   // vals: + val_b, lrelu
                        float b0 = b2[col], b1 = b2[col + 1];
                        v0 = lrelu(v0 + b0); v1 = lrelu(v1 + b1);
                        v2 = lrelu(v2 + b0); v3 = lrelu(v3 + b1);
                    }
                    *(__half2*)(outp + ((size_t)a * Bsz + m) * 128 + col) = __floats2half2_rn(v0, v1);
                    *(__half2*)(outp + ((size_t)a * Bsz + m + 8) * 128 + col) = __floats2half2_rn(v2, v3);
                }
            }
        }
    }
}

// ---------------- attention: 16 batch elts x 8 agents per block, fp16 in, pairs out ----
#define APITCH 36
__global__ __launch_bounds__(128) void attn_k() {
    __shared__ __half sS[128 * APITCH];
    __shared__ __half sK[128 * APITCH];
    int t = threadIdx.x;
    int b0 = blockIdx.x * 16;
    int bl = t >> 3, iq = t & 7;

    for (int kh = 0; kh < 4; kh++) {
        __syncthreads();
        {
            int lbl = t >> 3, ag = t & 7;
            size_t off = ((size_t)ag * Bsz + b0 + lbl) * 128 + kh * 32;
            const uint2* ps = (const uint2*)(g_selsh + off);
            const uint2* pk = (const uint2*)(g_keysh + off);
            uint2* ds = (uint2*)(sS + (lbl * 8 + ag) * APITCH);
            uint2* dk = (uint2*)(sK + (lbl * 8 + ag) * APITCH);
            #pragma unroll
            for (int j = 0; j < 8; j++) { ds[j] = ps[j]; dk[j] = pk[j]; }
        }
        __syncthreads();

        float sv[32];
        {
            const __half2* p = (const __half2*)(sS + (bl * 8 + iq) * APITCH);
            #pragma unroll
            for (int d = 0; d < 16; d++) {
                float2 f = __half22float2(p[d]);
                sv[2 * d] = f.x; sv[2 * d + 1] = f.y;
            }
        }
        float pj[8];
        #pragma unroll
        for (int j = 0; j < 8; j++) {
            const __half2* p = (const __half2*)(sK + (bl * 8 + j) * APITCH);
            float acc = 0.f;
            #pragma unroll
            for (int d = 0; d < 16; d++) {
                float2 f = __half22float2(p[d]);
                acc += sv[2 * d] * f.x + sv[2 * d + 1] * f.y;
            }
            pj[j] = acc * 0.17677669529663687f;
        }
        float mx = -1e30f;
        #pragma unroll
        for (int j = 0; j < 8; j++) if (j != iq) mx = fmaxf(mx, pj[j]);
        float sum = 0.f;
        #pragma unroll
        for (int j = 0; j < 8; j++) {
            pj[j] = (j == iq) ? 0.f : __expf(pj[j] - mx);
            sum += pj[j];
        }
        float inv = 1.f / sum;

        __syncthreads();
        {
            int lbl = t >> 3, ag = t & 7;
            size_t off = ((size_t)ag * Bsz + b0 + lbl) * 128 + kh * 32;
            const uint2* pv = (const uint2*)(g_valsh + off);
            uint2* ds = (uint2*)(sS + (lbl * 8 + ag) * APITCH);
            #pragma unroll
            for (int j = 0; j < 8; j++) ds[j] = pv[j];
        }
        __syncthreads();

        float ov[32];
        #pragma unroll
        for (int d = 0; d < 32; d++) ov[d] = 0.f;
        #pragma unroll
        for (int j = 0; j < 8; j++) {
            float w = pj[j] * inv;
            const __half2* p = (const __half2*)(sS + (bl * 8 + j) * APITCH);
            #pragma unroll
            for (int d = 0; d < 16; d++) {
                float2 f = __half22float2(p[d]);
                ov[2 * d]     += w * f.x;
                ov[2 * d + 1] += w * f.y;
            }
        }
        uint32_t* dst = g_ci + ((size_t)iq * Bsz + b0 + bl) * 256 + 128 + kh * 32;
        #pragma unroll
        for (int d4 = 0; d4 < 8; d4++) {
            uint4 u;
            u.x = splitpk(ov[d4 * 4]);     u.y = splitpk(ov[d4 * 4 + 1]);
            u.z = splitpk(ov[d4 * 4 + 2]); u.w = splitpk(ov[d4 * 4 + 3]);
            *(uint4*)(dst + d4 * 4) = u;
        }
    }
}

// ---------------- launch ----------------
extern "C" void kernel_launch(void* const* d_in, const int* in_sizes, int n_in,
                              void* d_out, int out_size) {
    const float* states = (const float*)d_in[0];
    const float* actions= (const float*)d_in[1];
    const float* enc_w  = (const float*)d_in[2];
    const float* enc_b  = (const float*)d_in[3];
    const float* aenc_w = (const float*)d_in[4];
    const float* aenc_b = (const float*)d_in[5];
    const float* key_w  = (const float*)d_in[6];
    const float* sel_w  = (const float*)d_in[7];
    const float* val_w  = (const float*)d_in[8];
    const float* val_b  = (const float*)d_in[9];
    const float* c1_w   = (const float*)d_in[10];
    const float* c1_b   = (const float*)d_in[11];
    const float* c2_w   = (const float*)d_in[12];
    const float* c2_b   = (const float*)d_in[13];
    float* out = (float*)d_out;

    void *p_ci, *p_keysh, *p_selsh, *p_valsh;
    void *p_Benc, *p_Baenc, *p_Bc1, *p_Wkp, *p_Wsp, *p_Wvp;
    cudaGetSymbolAddress(&p_ci,   g_ci);
    cudaGetSymbolAddress(&p_keysh,g_keysh);
    cudaGetSymbolAddress(&p_selsh,g_selsh);
    cudaGetSymbolAddress(&p_valsh,g_valsh);
    cudaGetSymbolAddress(&p_Benc, g_Benc);
    cudaGetSymbolAddress(&p_Baenc,g_Baenc);
    cudaGetSymbolAddress(&p_Bc1,  g_Bc1);
    cudaGetSymbolAddress(&p_Wkp,  g_Wkp);
    cudaGetSymbolAddress(&p_Wsp,  g_Wsp);
    cudaGetSymbolAddress(&p_Wvp,  g_Wvp);

    cudaFuncSetAttribute(gemm_fused<1, 1, 1>, cudaFuncAttributeMaxDynamicSharedMemorySize, 122880);
    cudaFuncSetAttribute(gemm_fused<2, 0, 2>, cudaFuncAttributeMaxDynamicSharedMemorySize, 163840);
    cudaFuncSetAttribute(gemm_fused<0, 2, 0>, cudaFuncAttributeMaxDynamicSharedMemorySize, 40960);

    bn_partial_k<<<dim3(32, 8), 320>>>(states, actions);
    bn_final_k<<<8, 160>>>();
    pack_w<<<dim3(10, 8), 256>>>(enc_w,  (__half*)p_Benc, 160, 0, 1);
    pack_w<<<dim3(2, 8),  256>>>(aenc_w, (__half*)p_Baenc, 32, 0, 1);
    pack_w<<<dim3(16, 8), 256>>>(c1_w,   (__half*)p_Bc1,  256, 0, 1);
    pack_w<<<dim3(8, 1),  256>>>(key_w,  (__half*)p_Wkp,  128, 1, 0);
    pack_w<<<dim3(8, 1),  256>>>(sel_w,  (__half*)p_Wsp,  128, 1, 0);
    pack_w<<<dim3(8, 1),  256>>>(val_w,  (__half*)p_Wvp,  128, 1, 0);

    dim3 gg(256, 1, 8);
    // E1: sa_enc -> ci[:,0:128] pairs, then tile @ Ws -> sels
    gemm_fused<1, 1, 1><<<gg, 256, 122880>>>(
        nullptr, 0, states, actions,
        (const __half*)p_Benc, 128L * 320, enc_b, 128,
        (uint32_t*)p_ci, 256,
        (const __half*)p_Wsp, nullptr, nullptr,
        (__half*)p_selsh, nullptr,
        nullptr, nullptr, nullptr, 160);
    // E2: a_enc tile (no global write), tile @ Wk -> keys, tile @ Wv (+val_b, lrelu) -> vals
    gemm_fused<2, 0, 2><<<gg, 256, 163840>>>(
        nullptr, 0, states, actions,
        (const __half*)p_Baenc, 128L * 64, aenc_b, 128,
        nullptr, 0,
        (const __half*)p_Wkp, (const __half*)p_Wvp, val_b,
        (__half*)p_keysh, (__half*)p_valsh,
        nullptr, nullptr, nullptr, 32);
    // attention -> ci[:,128:256] pairs
    attn_k<<<Bsz / 16, 128>>>();
    // E3: c1 + q fused
    gemm_fused<0, 2, 0><<<gg, 256, 40960>>>(
        (const uint32_t*)p_ci, 256, nullptr, nullptr,
        (const __half*)p_Bc1, 128L * 512, c1_b, 128,
        nullptr, 0,
        nullptr, nullptr, nullptr,
        nullptr, nullptr,
        c2_w, c2_b, out, 256);
}

// round 6
// speedup vs baseline: 1.0702x; 1.0702x over previous
#include <cuda_runtime.h>
#include <cuda_fp16.h>
#include <cstdint>
#include <cstddef>

#define A_   8
#define Bsz  32768
#define EPSB 1e-5f

// ---------------- static scratch ----------------
__device__ float g_part[8 * 32 * 160 * 2];
__device__ float g_mean[8 * 160];
__device__ float g_istd[8 * 160];
// pre-split (hi,lo) fp16 pairs, 1 uint32 per element (value = hi+lo)
__device__ __align__(128) uint32_t g_sa  [(size_t)A_ * Bsz * 128];   // sa_enc pairs
__device__ __align__(128) uint32_t g_aenc[(size_t)A_ * Bsz * 128];   // a_enc pairs
// plain fp16 tensors
__device__ __align__(128) __half g_keysh[(size_t)A_ * Bsz * 128];
__device__ __align__(128) __half g_selsh[(size_t)A_ * Bsz * 128];
__device__ __align__(128) __half g_valsh[(size_t)A_ * Bsz * 128];
__device__ __align__(128) __half g_atth [(size_t)A_ * Bsz * 128];    // attended, fp16
// dup-packed fp16 weights: [agent][n][K'=2K]
__device__ __align__(128) __half g_Benc [(size_t)8 * 128 * 320];
__device__ __align__(128) __half g_Baenc[(size_t)8 * 128 * 64];
__device__ __align__(128) __half g_Bc1  [(size_t)8 * 128 * 512];
__device__ __align__(128) __half g_Bhk  [(size_t)128 * 256];
__device__ __align__(128) __half g_Bhs  [(size_t)128 * 256];
__device__ __align__(128) __half g_Bhv  [(size_t)128 * 256];

__device__ __forceinline__ float lrelu(float x) { return fmaxf(x, 0.01f * x); }
__device__ __forceinline__ uint32_t smem_u32(const void* p) {
    uint32_t a;
    asm("{ .reg .u64 t; cvta.to.shared.u64 t, %1; cvt.u32.u64 %0, t; }" : "=r"(a) : "l"(p));
    return a;
}
__device__ __forceinline__ void ldsm4(uint32_t* r, uint32_t addr) {
    asm volatile("ldmatrix.sync.aligned.m8n8.x4.shared.b16 {%0,%1,%2,%3}, [%4];"
        : "=r"(r[0]), "=r"(r[1]), "=r"(r[2]), "=r"(r[3]) : "r"(addr));
}
__device__ __forceinline__ void mma16816(float* d, const uint32_t* a, const uint32_t* b) {
    asm volatile("mma.sync.aligned.m16n8k16.row.col.f32.f16.f16.f32 "
        "{%0,%1,%2,%3}, {%4,%5,%6,%7}, {%8,%9}, {%0,%1,%2,%3};"
        : "+f"(d[0]), "+f"(d[1]), "+f"(d[2]), "+f"(d[3])
        : "r"(a[0]), "r"(a[1]), "r"(a[2]), "r"(a[3]), "r"(b[0]), "r"(b[1]));
}
#define CP16(s, g) asm volatile("cp.async.cg.shared.global [%0], [%1], 16;" :: "r"(s), "l"(g))
#define CPCOMMIT() asm volatile("cp.async.commit_group;" ::: "memory")
#define CPWAIT1()  asm volatile("cp.async.wait_group 1;" ::: "memory")
#define CPWAIT0()  asm volatile("cp.async.wait_group 0;" ::: "memory")

__device__ __forceinline__ uint32_t pkh2(__half a, __half b) {
    __half2 h = __halves2half2(a, b);
    return *(uint32_t*)&h;
}
__device__ __forceinline__ uint32_t splitpk(float x) {
    __half h = __float2half_rn(x);
    __half l = __float2half_rn(x - __half2float(h));
    return pkh2(h, l);
}

// ---------------- BatchNorm stats ----------------
__global__ void bn_partial_k(const float* __restrict__ states,
                             const float* __restrict__ actions) {
    int a = blockIdx.y, chunk = blockIdx.x;
    int t = threadIdx.x;
    int f = t % 160, r0 = t / 160;
    size_t sb = (size_t)a * Bsz * 128, ab = (size_t)a * Bsz * 32;
    int row0 = chunk * 1024;
    float s = 0.f, s2 = 0.f;
    if (f < 128) {
        const float* p = states + sb + (size_t)(row0 + r0) * 128 + f;
        #pragma unroll 4
        for (int r = 0; r < 512; r++) { float v = *p; p += 256; s += v; s2 += v * v; }
    } else {
        const float* p = actions + ab + (size_t)(row0 + r0) * 32 + (f - 128);
        #pragma unroll 4
        for (int r = 0; r < 512; r++) { float v = *p; p += 64; s += v; s2 += v * v; }
    }
    __shared__ float sh[640];
    sh[t] = s; sh[320 + t] = s2;
    __syncthreads();
    if (t < 160) {
        float ss = sh[t] + sh[t + 160];
        float qq = sh[320 + t] + sh[320 + t + 160];
        int o = ((a * 32 + chunk) * 160 + t) * 2;
        g_part[o] = ss; g_part[o + 1] = qq;
    }
}

__global__ void bn_final_k() {
    int a = blockIdx.x, f = threadIdx.x;
    float s = 0.f, s2 = 0.f;
    for (int c = 0; c < 32; c++) {
        int o = ((a * 32 + c) * 160 + f) * 2;
        s += g_part[o]; s2 += g_part[o + 1];
    }
    float m = s * (1.f / 32768.f);
    float v = s2 * (1.f / 32768.f) - m * m;
    g_mean[a * 160 + f] = m;
    g_istd[a * 160 + f] = rsqrtf(v + EPSB);
}

// ---------------- weight pack: transpose + fp16 + dup ----------------
// mode 0: src [a][k][n=128]    mode 1: heads src [(n>>5)][k][n&31]
__global__ void pack_w(const float* __restrict__ src, __half* __restrict__ dst,
                       int K, int mode) {
    __shared__ float tile[16][128];
    int a = blockIdx.y, kt = blockIdx.x, t = threadIdx.x;
    int k0 = kt * 16;
    #pragma unroll
    for (int i = 0; i < 2; i++) {
        int p = t + i * 256;
        int kk = p >> 5, n4 = (p & 31) * 4;
        float4 v;
        if (mode == 0)
            v = *(const float4*)(src + ((size_t)a * K + k0 + kk) * 128 + n4);
        else
            v = *(const float4*)(src + ((size_t)(n4 >> 5) * 128 + k0 + kk) * 32 + (n4 & 31));
        tile[kk][n4] = v.x; tile[kk][n4 + 1] = v.y;
        tile[kk][n4 + 2] = v.z; tile[kk][n4 + 3] = v.w;
    }
    __syncthreads();
    int K2 = 2 * K;
    #pragma unroll
    for (int i = 0; i < 2; i++) {
        int p = t + i * 256;
        int n = p >> 2, kq = p & 3;
        __half h[4];
        #pragma unroll
        for (int j = 0; j < 4; j++)
            h[j] = __float2half_rn(tile[kq * 4 + j][n]);
        uint4 u;
        u.x = pkh2(h[0], h[0]); u.y = pkh2(h[1], h[1]);
        u.z = pkh2(h[2], h[2]); u.w = pkh2(h[3], h[3]);
        *(uint4*)(dst + (size_t)a * 128 * K2 + (size_t)n * K2 + kt * 32 + kq * 8) = u;
    }
}

// ---------------- mma.sync split GEMM (A = h+l exact, B = hi dup) ----------------
// SRC: 0 pairs via cp.async (Apairs,lda), 1 BN(concat) K=160, 2 BN(actions) K=32,
//      3 mixed: k<128 pairs from Apairs, k>=128 fp16 from att (c1 input)
// EPI: 0 raw fp16, 1 bias+lrelu -> pairs, 2 bias+lrelu + c2 dot -> qout, 3 bias+lrelu fp16
#define PITCH 80
#define STAGE 20480

template<int SRC, int EPI>
__global__ __launch_bounds__(256, 2) void gemm_mma(
    const uint32_t* __restrict__ Apairs, int lda,
    const float* __restrict__ states, const float* __restrict__ actions,
    const __half* __restrict__ att,
    const __half* __restrict__ Bt, long wstride,
    const float* __restrict__ bias, int bstride,
    void* __restrict__ Cout, int ldc,
    const float* __restrict__ c2w, const float* __restrict__ c2b,
    float* __restrict__ qout,
    int Kdim) {

    __shared__ __align__(16) char sm[2][STAGE];
    int tid = threadIdx.x, lane = tid & 31, wid = tid >> 5;
    int wm = wid & 3, wn = wid >> 2;
    int a = blockIdx.z, m0 = blockIdx.x * 128;
    int K2 = Kdim * 2;
    int nch = Kdim >> 4;

    const float* mp = g_mean + a * 160;
    const float* ip = g_istd + a * 160;
    size_t sbo = (size_t)a * Bsz * 128, abo = (size_t)a * Bsz * 32;
    const uint32_t* Ap = (SRC == 0 || SRC == 3) ? (Apairs + (size_t)a * Bsz * lda) : nullptr;
    const __half* Atp = (SRC == 3) ? (att + (size_t)a * Bsz * 128) : nullptr;
    const __half* Bp = Bt + (size_t)a * wstride;

    uint32_t smu = smem_u32(sm);

    float4 av[2];     // SRC 1/2
    uint4 avu[2];     // SRC 3
    auto loadA = [&](int c) {
        #pragma unroll
        for (int i = 0; i < 2; i++) {
            int p = tid + i * 256;
            int row = p >> 2, kq = p & 3;
            int k = c * 16 + kq * 4;
            if (SRC == 1) {
                float4 v;
                if (k < 128) v = *(const float4*)(states + sbo + (size_t)(m0 + row) * 128 + k);
                else         v = *(const float4*)(actions + abo + (size_t)(m0 + row) * 32 + (k - 128));
                v.x = (v.x - mp[k    ]) * ip[k    ];
                v.y = (v.y - mp[k + 1]) * ip[k + 1];
                v.z = (v.z - mp[k + 2]) * ip[k + 2];
                v.w = (v.w - mp[k + 3]) * ip[k + 3];
                av[i] = v;
            } else if (SRC == 2) {
                float4 v = *(const float4*)(actions + abo + (size_t)(m0 + row) * 32 + k);
                v.x = (v.x - mp[128 + k]) * ip[128 + k];
                v.y = (v.y - mp[129 + k]) * ip[129 + k];
                v.z = (v.z - mp[130 + k]) * ip[130 + k];
                v.w = (v.w - mp[131 + k]) * ip[131 + k];
                av[i] = v;
            } else if (SRC == 3) {
                if (k < 128) {
                    avu[i] = *(const uint4*)(Ap + (size_t)(m0 + row) * lda + k);
                } else {
                    uint2 t2 = *(const uint2*)(Atp + (size_t)(m0 + row) * 128 + (k - 128));
                    avu[i].x = t2.x & 0xFFFFu;  avu[i].y = t2.x >> 16;
                    avu[i].z = t2.y & 0xFFFFu;  avu[i].w = t2.y >> 16;
                }
            }
        }
    };
    auto stsA = [&](int buf) {
        #pragma unroll
        for (int i = 0; i < 2; i++) {
            int p = tid + i * 256;
            int row = p >> 2, kq = p & 3;
            uint4 u;
            if (SRC == 3) u = avu[i];
            else {
                float4 v = av[i];
                u.x = splitpk(v.x); u.y = splitpk(v.y);
                u.z = splitpk(v.z); u.w = splitpk(v.w);
            }
            *(uint4*)(sm[buf] + row * PITCH + kq * 16) = u;
        }
    };
    auto cpA = [&](int c, int buf) {
        #pragma unroll
        for (int i = 0; i < 2; i++) {
            int p = tid + i * 256;
            int row = p >> 2, seg = p & 3;
            const uint32_t* g = Ap + (size_t)(m0 + row) * lda + c * 16 + seg * 4;
            CP16(smu + buf * STAGE + row * PITCH + seg * 16, g);
        }
    };
    auto cpB = [&](int c, int buf) {
        #pragma unroll
        for (int i = 0; i < 2; i++) {
            int s = tid + i * 256;
            int n = s >> 2, seg = s & 3;
            const __half* g = Bp + (size_t)n * K2 + c * 32 + seg * 8;
            CP16(smu + buf * STAGE + 10240 + n * PITCH + seg * 16, g);
        }
    };

    int r = lane & 7, q = lane >> 3;
    uint32_t a_off[2], b_off[4];
    #pragma unroll
    for (int mt = 0; mt < 2; mt++)
        a_off[mt] = (uint32_t)((wm * 32 + mt * 16 + (q & 1) * 8 + r) * PITCH + (q >> 1) * 16);
    #pragma unroll
    for (int np = 0; np < 4; np++)
        b_off[np] = (uint32_t)(10240 + (wn * 64 + np * 16 + (q >> 1) * 8 + r) * PITCH + (q & 1) * 16);

    float acc[2][8][4];
    #pragma unroll
    for (int mt = 0; mt < 2; mt++)
        #pragma unroll
        for (int nt = 0; nt < 8; nt++)
            #pragma unroll
            for (int i = 0; i < 4; i++) acc[mt][nt][i] = 0.f;

    if (SRC == 0) { cpA(0, 0); cpB(0, 0); CPCOMMIT(); }
    else          { loadA(0);  cpB(0, 0); CPCOMMIT(); }

    for (int c = 0; c < nch; c++) {
        int buf = c & 1;
        if (SRC == 0) {
            if (c + 1 < nch) { cpA(c + 1, buf ^ 1); cpB(c + 1, buf ^ 1); CPCOMMIT(); CPWAIT1(); }
            else             { CPWAIT0(); }
        } else {
            if (c + 1 < nch) { cpB(c + 1, buf ^ 1); CPCOMMIT(); }
            stsA(buf);
            if (c + 1 < nch) { loadA(c + 1); CPWAIT1(); }
            else             { CPWAIT0(); }
        }
        __syncthreads();
        uint32_t bb = smu + buf * STAGE;
        #pragma unroll
        for (int ks = 0; ks < 2; ks++) {
            uint32_t af[2][4], bf[4][4];
            #pragma unroll
            for (int mt = 0; mt < 2; mt++) ldsm4(af[mt], bb + a_off[mt] + ks * 32);
            #pragma unroll
            for (int np = 0; np < 4; np++) ldsm4(bf[np], bb + b_off[np] + ks * 32);
            #pragma unroll
            for (int mt = 0; mt < 2; mt++)
                #pragma unroll
                for (int nt = 0; nt < 8; nt++)
                    mma16816(acc[mt][nt], af[mt], &bf[nt >> 1][(nt & 1) * 2]);
        }
        __syncthreads();
    }

    int g = lane >> 2, tig = lane & 3;

    if (EPI == 2) {
        float qp[4] = {0.f, 0.f, 0.f, 0.f};
        #pragma unroll
        for (int mt = 0; mt < 2; mt++)
            #pragma unroll
            for (int nt = 0; nt < 8; nt++) {
                int col = wn * 64 + nt * 8 + 2 * tig;
                float b0 = bias[a * bstride + col], b1 = bias[a * bstride + col + 1];
                float w0 = c2w[a * 128 + col], w1 = c2w[a * 128 + col + 1];
                qp[mt * 2]     += lrelu(acc[mt][nt][0] + b0) * w0 + lrelu(acc[mt][nt][1] + b1) * w1;
                qp[mt * 2 + 1] += lrelu(acc[mt][nt][2] + b0) * w0 + lrelu(acc[mt][nt][3] + b1) * w1;
            }
        #pragma unroll
        for (int j = 0; j < 4; j++) {
            qp[j] += __shfl_xor_sync(0xffffffffu, qp[j], 1);
            qp[j] += __shfl_xor_sync(0xffffffffu, qp[j], 2);
        }
        __syncthreads();
        float* qsm = (float*)sm;
        if (tig == 0) {
            #pragma unroll
            for (int j = 0; j < 4; j++) {
                int rl = wm * 32 + (j >> 1) * 16 + (j & 1) * 8 + g;
                qsm[rl * 2 + wn] = qp[j];
            }
        }
        __syncthreads();
        if (tid < 128)
            qout[(size_t)a * Bsz + m0 + tid] = qsm[tid * 2] + qsm[tid * 2 + 1] + c2b[a];
    } else {
        #pragma unroll
        for (int mt = 0; mt < 2; mt++) {
            int m = m0 + wm * 32 + mt * 16 + g;
            #pragma unroll
            for (int nt = 0; nt < 8; nt++) {
                int col = wn * 64 + nt * 8 + 2 * tig;
                float v0 = acc[mt][nt][0], v1 = acc[mt][nt][1];
                float v2 = acc[mt][nt][2], v3 = acc[mt][nt][3];
                if (EPI == 1 || EPI == 3) {
                    float b0 = bias[a * bstride + col], b1 = bias[a * bstride + col + 1];
                    v0 = lrelu(v0 + b0); v1 = lrelu(v1 + b1);
                    v2 = lrelu(v2 + b0); v3 = lrelu(v3 + b1);
                }
                if (EPI == 1) {
                    uint32_t* Cp = (uint32_t*)Cout;
                    uint2 u0; u0.x = splitpk(v0); u0.y = splitpk(v1);
                    uint2 u1; u1.x = splitpk(v2); u1.y = splitpk(v3);
                    *(uint2*)(Cp + ((size_t)a * Bsz + m) * ldc + col) = u0;
                    *(uint2*)(Cp + ((size_t)a * Bsz + m + 8) * ldc + col) = u1;
                } else {
                    __half* Cp = (__half*)Cout;
                    *(__half2*)(Cp + ((size_t)a * Bsz + m) * ldc + col) = __floats2half2_rn(v0, v1);
                    *(__half2*)(Cp + ((size_t)a * Bsz + m + 8) * ldc + col) = __floats2half2_rn(v2, v3);
                }
            }
        }
    }
}

// ---------------- keys+vals: A resident once, two B streams ----------------
#define KV_APITCH 528
#define KV_BOFF   67584
__global__ __launch_bounds__(256, 2) void kv_k(
    const uint32_t* __restrict__ Apairs,
    const __half* __restrict__ Bk, const __half* __restrict__ Bv,
    const float* __restrict__ valb,
    __half* __restrict__ keysh, __half* __restrict__ valsh) {

    extern __shared__ __align__(16) char sm[];
    uint32_t smu = smem_u32(sm);
    int tid = threadIdx.x, lane = tid & 31, wid = tid >> 5;
    int wm = wid & 3, wn = wid >> 2;
    int a = blockIdx.y, m0 = blockIdx.x * 128;
    const uint32_t* Ap = Apairs + (size_t)a * Bsz * 128;

    // whole A tile (128 rows x 128 pairs = 64KB) resident
    #pragma unroll
    for (int i = 0; i < 16; i++) {
        int idx = tid + 256 * i;
        int row = idx >> 5, seg = idx & 31;
        CP16(smu + row * KV_APITCH + seg * 16, Ap + (size_t)(m0 + row) * 128 + seg * 4);
    }
    auto cpB = [&](const __half* Bsrc, int c, int buf) {
        #pragma unroll
        for (int i = 0; i < 2; i++) {
            int s = tid + i * 256;
            int n = s >> 2, seg = s & 3;
            CP16(smu + KV_BOFF + buf * 10240 + n * PITCH + seg * 16,
                 Bsrc + (size_t)n * 256 + c * 32 + seg * 8);
        }
    };
    cpB(Bk, 0, 0); CPCOMMIT();

    int r = lane & 7, q = lane >> 3;
    uint32_t a_off[2], b_off[4];
    #pragma unroll
    for (int mt = 0; mt < 2; mt++)
        a_off[mt] = (uint32_t)((wm * 32 + mt * 16 + (q & 1) * 8 + r) * KV_APITCH + (q >> 1) * 16);
    #pragma unroll
    for (int np = 0; np < 4; np++)
        b_off[np] = (uint32_t)(KV_BOFF + (wn * 64 + np * 16 + (q >> 1) * 8 + r) * PITCH + (q & 1) * 16);

    float acc[2][8][4];
    #pragma unroll
    for (int mt = 0; mt < 2; mt++)
        #pragma unroll
        for (int nt = 0; nt < 8; nt++)
            #pragma unroll
            for (int i = 0; i < 4; i++) acc[mt][nt][i] = 0.f;

    int g = lane >> 2, tig = lane & 3;

    for (int c = 0; c < 16; c++) {
        int buf = c & 1;
        if (c + 1 < 16) {
            int cn = c + 1;
            cpB(cn < 8 ? Bk : Bv, cn & 7, buf ^ 1);
            CPCOMMIT(); CPWAIT1();
        } else {
            CPWAIT0();
        }
        __syncthreads();
        int kc = c & 7;
        #pragma unroll
        for (int ks = 0; ks < 2; ks++) {
            uint32_t af[2][4], bf[4][4];
            #pragma unroll
            for (int mt = 0; mt < 2; mt++)
                ldsm4(af[mt], smu + a_off[mt] + kc * 64 + ks * 32);
            #pragma unroll
            for (int np = 0; np < 4; np++)
                ldsm4(bf[np], smu + b_off[np] + (buf * 10240) + ks * 32);
            #pragma unroll
            for (int mt = 0; mt < 2; mt++)
                #pragma unroll
                for (int nt = 0; nt < 8; nt++)
                    mma16816(acc[mt][nt], af[mt], &bf[nt >> 1][(nt & 1) * 2]);
        }
        __syncthreads();

        if (c == 7 || c == 15) {
            bool isv = (c == 15);
            __half* outp = isv ? valsh : keysh;
            #pragma unroll
            for (int mt = 0; mt < 2; mt++) {
                int m = m0 + wm * 32 + mt * 16 + g;
                #pragma unroll
                for (int nt = 0; nt < 8; nt++) {
                    int col = wn * 64 + nt * 8 + 2 * tig;
                    float v0 = acc[mt][nt][0], v1 = acc[mt][nt][1];
                    float v2 = acc[mt][nt][2], v3 = acc[mt][nt][3];
                    if (isv) {
                        float b0 = valb[col], b1 = valb[col + 1];
                        v0 = lrelu(v0 + b0); v1 = lrelu(v1 + b1);
                        v2 = lrelu(v2 + b0); v3 = lrelu(v3 + b1);
                    }
                    *(__half2*)(outp + ((size_t)a * Bsz + m) * 128 + col) = __floats2half2_rn(v0, v1);
                    *(__half2*)(outp + ((size_t)a * Bsz + m + 8) * 128 + col) = __floats2half2_rn(v2, v3);
                    acc[mt][nt][0] = 0.f; acc[mt][nt][1] = 0.f;
                    acc[mt][nt][2] = 0.f; acc[mt][nt][3] = 0.f;
                }
            }
        }
    }
}

// ---------------- attention: 16 batch elts x 8 agents per block, fp16 in/out ----
#define APITCH 36
__global__ __launch_bounds__(128) void attn_k() {
    __shared__ __half sS[128 * APITCH];
    __shared__ __half sK[128 * APITCH];
    int t = threadIdx.x;
    int b0 = blockIdx.x * 16;
    int bl = t >> 3, iq = t & 7;

    for (int kh = 0; kh < 4; kh++) {
        __syncthreads();
        {
            int lbl = t >> 3, ag = t & 7;
            size_t off = ((size_t)ag * Bsz + b0 + lbl) * 128 + kh * 32;
            const uint2* ps = (const uint2*)(g_selsh + off);
            const uint2* pk = (const uint2*)(g_keysh + off);
            uint2* ds = (uint2*)(sS + (lbl * 8 + ag) * APITCH);
            uint2* dk = (uint2*)(sK + (lbl * 8 + ag) * APITCH);
            #pragma unroll
            for (int j = 0; j < 8; j++) { ds[j] = ps[j]; dk[j] = pk[j]; }
        }
        __syncthreads();

        float sv[32];
        {
            const __half2* p = (const __half2*)(sS + (bl * 8 + iq) * APITCH);
            #pragma unroll
            for (int d = 0; d < 16; d++) {
                float2 f = __half22float2(p[d]);
                sv[2 * d] = f.x; sv[2 * d + 1] = f.y;
            }
        }
        float pj[8];
        #pragma unroll
        for (int j = 0; j < 8; j++) {
            const __half2* p = (const __half2*)(sK + (bl * 8 + j) * APITCH);
            float acc = 0.f;
            #pragma unroll
            for (int d = 0; d < 16; d++) {
                float2 f = __half22float2(p[d]);
                acc += sv[2 * d] * f.x + sv[2 * d + 1] * f.y;
            }
            pj[j] = acc * 0.17677669529663687f;
        }
        float mx = -1e30f;
        #pragma unroll
        for (int j = 0; j < 8; j++) if (j != iq) mx = fmaxf(mx, pj[j]);
        float sum = 0.f;
        #pragma unroll
        for (int j = 0; j < 8; j++) {
            pj[j] = (j == iq) ? 0.f : __expf(pj[j] - mx);
            sum += pj[j];
        }
        float inv = 1.f / sum;

        __syncthreads();
        {
            int lbl = t >> 3, ag = t & 7;
            size_t off = ((size_t)ag * Bsz + b0 + lbl) * 128 + kh * 32;
            const uint2* pv = (const uint2*)(g_valsh + off);
            uint2* ds = (uint2*)(sS + (lbl * 8 + ag) * APITCH);
            #pragma unroll
            for (int j = 0; j < 8; j++) ds[j] = pv[j];
        }
        __syncthreads();

        float ov[32];
        #pragma unroll
        for (int d = 0; d < 32; d++) ov[d] = 0.f;
        #pragma unroll
        for (int j = 0; j < 8; j++) {
            float w = pj[j] * inv;
            const __half2* p = (const __half2*)(sS + (bl * 8 + j) * APITCH);
            #pragma unroll
            for (int d = 0; d < 16; d++) {
                float2 f = __half22float2(p[d]);
                ov[2 * d]     += w * f.x;
                ov[2 * d + 1] += w * f.y;
            }
        }
        __half* dst = g_atth + ((size_t)iq * Bsz + b0 + bl) * 128 + kh * 32;
        #pragma unroll
        for (int g4 = 0; g4 < 4; g4++) {
            uint4 u;
            u.x = *(uint32_t*)&(__half2&)*(__half2[]){__floats2half2_rn(ov[g4*8+0], ov[g4*8+1])};
            u.x = 0; // placeholder overwritten below
            __half2 h0 = __floats2half2_rn(ov[g4*8+0], ov[g4*8+1]);
            __half2 h1 = __floats2half2_rn(ov[g4*8+2], ov[g4*8+3]);
            __half2 h2 = __floats2half2_rn(ov[g4*8+4], ov[g4*8+5]);
            __half2 h3 = __floats2half2_rn(ov[g4*8+6], ov[g4*8+7]);
            u.x = *(uint32_t*)&h0; u.y = *(uint32_t*)&h1;
            u.z = *(uint32_t*)&h2; u.w = *(uint32_t*)&h3;
            *(uint4*)(dst + g4 * 8) = u;
        }
    }
}

// ---------------- launch ----------------
extern "C" void kernel_launch(void* const* d_in, const int* in_sizes, int n_in,
                              void* d_out, int out_size) {
    const float* states = (const float*)d_in[0];
    const float* actions= (const float*)d_in[1];
    const float* enc_w  = (const float*)d_in[2];
    const float* enc_b  = (const float*)d_in[3];
    const float* aenc_w = (const float*)d_in[4];
    const float* aenc_b = (const float*)d_in[5];
    const float* key_w  = (const float*)d_in[6];
    const float* sel_w  = (const float*)d_in[7];
    const float* val_w  = (const float*)d_in[8];
    const float* val_b  = (const float*)d_in[9];
    const float* c1_w   = (const float*)d_in[10];
    const float* c1_b   = (const float*)d_in[11];
    const float* c2_w   = (const float*)d_in[12];
    const float* c2_b   = (const float*)d_in[13];
    float* out = (float*)d_out;

    void *p_sa, *p_aenc, *p_keysh, *p_selsh, *p_valsh, *p_atth;
    void *p_Benc, *p_Baenc, *p_Bc1, *p_Bhk, *p_Bhs, *p_Bhv;
    cudaGetSymbolAddress(&p_sa,   g_sa);
    cudaGetSymbolAddress(&p_aenc, g_aenc);
    cudaGetSymbolAddress(&p_keysh,g_keysh);
    cudaGetSymbolAddress(&p_selsh,g_selsh);
    cudaGetSymbolAddress(&p_valsh,g_valsh);
    cudaGetSymbolAddress(&p_atth, g_atth);
    cudaGetSymbolAddress(&p_Benc, g_Benc);
    cudaGetSymbolAddress(&p_Baenc,g_Baenc);
    cudaGetSymbolAddress(&p_Bc1,  g_Bc1);
    cudaGetSymbolAddress(&p_Bhk,  g_Bhk);
    cudaGetSymbolAddress(&p_Bhs,  g_Bhs);
    cudaGetSymbolAddress(&p_Bhv,  g_Bhv);

    cudaFuncSetAttribute(kv_k, cudaFuncAttributeMaxDynamicSharedMemorySize, 88064);

    bn_partial_k<<<dim3(32, 8), 320>>>(states, actions);
    bn_final_k<<<8, 160>>>();
    pack_w<<<dim3(10, 8), 256>>>(enc_w,  (__half*)p_Benc, 160, 0);
    pack_w<<<dim3(2, 8),  256>>>(aenc_w, (__half*)p_Baenc, 32, 0);
    pack_w<<<dim3(16, 8), 256>>>(c1_w,   (__half*)p_Bc1,  256, 0);
    pack_w<<<dim3(8, 1),  256>>>(key_w,  (__half*)p_Bhk,  128, 1);
    pack_w<<<dim3(8, 1),  256>>>(sel_w,  (__half*)p_Bhs,  128, 1);
    pack_w<<<dim3(8, 1),  256>>>(val_w,  (__half*)p_Bhv,  128, 1);

    dim3 gg(256, 1, 8);
    // sa_enc -> g_sa pairs (BN concat, K=160, bias+lrelu)
    gemm_mma<1, 1><<<gg, 256>>>(nullptr, 0, states, actions, nullptr,
                                (const __half*)p_Benc, 128L * 320,
                                enc_b, 128, p_sa, 128,
                                nullptr, nullptr, nullptr, 160);
    // a_enc -> g_aenc pairs (BN actions, K=32, bias+lrelu)
    gemm_mma<2, 1><<<gg, 256>>>(nullptr, 0, states, actions, nullptr,
                                (const __half*)p_Baenc, 128L * 64,
                                aenc_b, 128, p_aenc, 128,
                                nullptr, nullptr, nullptr, 32);
    // keys + vals (A read once)
    kv_k<<<dim3(256, 8), 256, 88064>>>((const uint32_t*)p_aenc,
                                       (const __half*)p_Bhk, (const __half*)p_Bhv,
                                       val_b, (__half*)p_keysh, (__half*)p_valsh);
    // sels = sa_enc @ Ws -> fp16
    gemm_mma<0, 0><<<gg, 256>>>((const uint32_t*)p_sa, 128, nullptr, nullptr, nullptr,
                                (const __half*)p_Bhs, 0,
                                nullptr, 0, p_selsh, 128,
                                nullptr, nullptr, nullptr, 128);
    // attention -> g_atth fp16
    attn_k<<<Bsz / 16, 128>>>();
    // c1 + q fused (A: sa pairs + att fp16)
    gemm_mma<3, 2><<<gg, 256>>>((const uint32_t*)p_sa, 128, nullptr, nullptr,
                                (const __half*)p_atth,
                                (const __half*)p_Bc1, 128L * 512,
                                c1_b, 128, nullptr, 0,
                                c2_w, c2_b, out, 256);
}

// round 7
// speedup vs baseline: 1.3940x; 1.3025x over previous
#include <cuda_runtime.h>
#include <cuda_fp16.h>
#include <cstdint>
#include <cstddef>

#define A_   8
#define Bsz  32768
#define EPSB 1e-5f

// ---------------- static scratch ----------------
__device__ float g_part[8 * 32 * 160 * 2];
__device__ float g_mean[8 * 160];
__device__ float g_istd[8 * 160];
// pre-split (hi,lo) fp16 pairs, 1 uint32 per element (value = hi+lo)
__device__ __align__(128) uint32_t g_sa[(size_t)A_ * Bsz * 128];
// plain fp16 tensors
__device__ __align__(128) __half g_keysh[(size_t)A_ * Bsz * 128];
__device__ __align__(128) __half g_selsh[(size_t)A_ * Bsz * 128];
__device__ __align__(128) __half g_valsh[(size_t)A_ * Bsz * 128];
__device__ __align__(128) __half g_atth [(size_t)A_ * Bsz * 128];
// packed weights
__device__ __align__(128) __half g_Benc [(size_t)8 * 128 * 320];  // dup
__device__ __align__(128) __half g_Baenc[(size_t)8 * 128 * 64];   // dup
__device__ __align__(128) __half g_Bc1  [(size_t)8 * 128 * 384];  // mixed: dup[0,256) + single[256,384)
__device__ __align__(128) __half g_Wkp[128 * 128];                // nodup
__device__ __align__(128) __half g_Wsp[128 * 128];
__device__ __align__(128) __half g_Wvp[128 * 128];

__device__ __forceinline__ float lrelu(float x) { return fmaxf(x, 0.01f * x); }
__device__ __forceinline__ uint32_t smem_u32(const void* p) {
    uint32_t a;
    asm("{ .reg .u64 t; cvta.to.shared.u64 t, %1; cvt.u32.u64 %0, t; }" : "=r"(a) : "l"(p));
    return a;
}
__device__ __forceinline__ void ldsm4(uint32_t* r, uint32_t addr) {
    asm volatile("ldmatrix.sync.aligned.m8n8.x4.shared.b16 {%0,%1,%2,%3}, [%4];"
        : "=r"(r[0]), "=r"(r[1]), "=r"(r[2]), "=r"(r[3]) : "r"(addr));
}
__device__ __forceinline__ void mma16816(float* d, const uint32_t* a, const uint32_t* b) {
    asm volatile("mma.sync.aligned.m16n8k16.row.col.f32.f16.f16.f32 "
        "{%0,%1,%2,%3}, {%4,%5,%6,%7}, {%8,%9}, {%0,%1,%2,%3};"
        : "+f"(d[0]), "+f"(d[1]), "+f"(d[2]), "+f"(d[3])
        : "r"(a[0]), "r"(a[1]), "r"(a[2]), "r"(a[3]), "r"(b[0]), "r"(b[1]));
}
#define CP16(s, g) asm volatile("cp.async.cg.shared.global [%0], [%1], 16;" :: "r"(s), "l"(g))
#define CPCOMMIT() asm volatile("cp.async.commit_group;" ::: "memory")
#define CPWAIT1()  asm volatile("cp.async.wait_group 1;" ::: "memory")
#define CPWAIT0()  asm volatile("cp.async.wait_group 0;" ::: "memory")

__device__ __forceinline__ uint32_t pkh2(__half a, __half b) {
    __half2 h = __halves2half2(a, b);
    return *(uint32_t*)&h;
}
__device__ __forceinline__ uint32_t splitpk(float x) {
    __half h = __float2half_rn(x);
    __half l = __float2half_rn(x - __half2float(h));
    return pkh2(h, l);
}

#define PITCH 80
#define STAGE 20480
#define CHNK  10240

// ---------------- BatchNorm stats ----------------
__global__ void bn_partial_k(const float* __restrict__ states,
                             const float* __restrict__ actions) {
    int a = blockIdx.y, chunk = blockIdx.x;
    int t = threadIdx.x;
    int f = t % 160, r0 = t / 160;
    size_t sb = (size_t)a * Bsz * 128, ab = (size_t)a * Bsz * 32;
    int row0 = chunk * 1024;
    float s = 0.f, s2 = 0.f;
    if (f < 128) {
        const float* p = states + sb + (size_t)(row0 + r0) * 128 + f;
        #pragma unroll 4
        for (int r = 0; r < 512; r++) { float v = *p; p += 256; s += v; s2 += v * v; }
    } else {
        const float* p = actions + ab + (size_t)(row0 + r0) * 32 + (f - 128);
        #pragma unroll 4
        for (int r = 0; r < 512; r++) { float v = *p; p += 64; s += v; s2 += v * v; }
    }
    __shared__ float sh[640];
    sh[t] = s; sh[320 + t] = s2;
    __syncthreads();
    if (t < 160) {
        float ss = sh[t] + sh[t + 160];
        float qq = sh[320 + t] + sh[320 + t + 160];
        int o = ((a * 32 + chunk) * 160 + t) * 2;
        g_part[o] = ss; g_part[o + 1] = qq;
    }
}

__global__ void bn_final_k() {
    int a = blockIdx.x, f = threadIdx.x;
    float s = 0.f, s2 = 0.f;
    for (int c = 0; c < 32; c++) {
        int o = ((a * 32 + c) * 160 + f) * 2;
        s += g_part[o]; s2 += g_part[o + 1];
    }
    float m = s * (1.f / 32768.f);
    float v = s2 * (1.f / 32768.f) - m * m;
    g_mean[a * 160 + f] = m;
    g_istd[a * 160 + f] = rsqrtf(v + EPSB);
}

// ---------------- weight pack: transpose + fp16, dup or single, strided dst ----
// mode 0: src [a][k][n=128]    mode 1: heads src [(n>>5)][k][n&31]
__global__ void pack_w(const float* __restrict__ src, __half* __restrict__ dst,
                       int Ksrc, int mode, int dup, int dstStride, int dstOff) {
    __shared__ float tile[16][128];
    int a = blockIdx.y, kt = blockIdx.x, t = threadIdx.x;
    int k0 = kt * 16;
    #pragma unroll
    for (int i = 0; i < 2; i++) {
        int p = t + i * 256;
        int kk = p >> 5, n4 = (p & 31) * 4;
        float4 v;
        if (mode == 0)
            v = *(const float4*)(src + ((size_t)a * Ksrc + k0 + kk) * 128 + n4);
        else
            v = *(const float4*)(src + ((size_t)(n4 >> 5) * 128 + k0 + kk) * 32 + (n4 & 31));
        tile[kk][n4] = v.x; tile[kk][n4 + 1] = v.y;
        tile[kk][n4 + 2] = v.z; tile[kk][n4 + 3] = v.w;
    }
    __syncthreads();
    #pragma unroll
    for (int i = 0; i < 2; i++) {
        int p = t + i * 256;
        int n = p >> 2, kq = p & 3;
        __half h[4];
        #pragma unroll
        for (int j = 0; j < 4; j++)
            h[j] = __float2half_rn(tile[kq * 4 + j][n]);
        __half* base = dst + (size_t)a * 128 * dstStride + (size_t)n * dstStride + dstOff;
        if (dup) {
            uint4 u;
            u.x = pkh2(h[0], h[0]); u.y = pkh2(h[1], h[1]);
            u.z = pkh2(h[2], h[2]); u.w = pkh2(h[3], h[3]);
            *(uint4*)(base + kt * 32 + kq * 8) = u;
        } else {
            uint2 u;
            u.x = pkh2(h[0], h[1]); u.y = pkh2(h[2], h[3]);
            *(uint2*)(base + kt * 16 + kq * 4) = u;
        }
    }
}

// ---------------- fused sa_enc + sels ----------------
// Phase 1: sa = lrelu(BN(concat) @ enc_w + enc_b) -> pairs to g_sa + fp16 tile in smem
// Phase 2: sels = sa_tile @ Ws (nodup, resident) -> fp16
#define WSOFF 40960
__global__ __launch_bounds__(256, 2) void sa_sels_k(
    const float* __restrict__ states, const float* __restrict__ actions,
    const __half* __restrict__ Benc, const float* __restrict__ enc_b,
    const __half* __restrict__ Wsp,
    uint32_t* __restrict__ saout, __half* __restrict__ selsout) {

    extern __shared__ __align__(16) char sm[];
    uint32_t smu = smem_u32(sm);
    int tid = threadIdx.x, lane = tid & 31, wid = tid >> 5;
    int wm = wid & 3, wn = wid >> 2;
    int a = blockIdx.z, m0 = blockIdx.x * 128;

    // Ws resident (own commit group, drains with mainloop waits)
    #pragma unroll
    for (int i = 0; i < 8; i++) {
        int s = tid + 256 * i;
        int n = s >> 4, sr = s & 15;
        CP16(smu + WSOFF + (sr >> 2) * CHNK + n * PITCH + (sr & 3) * 16,
             Wsp + (size_t)n * 128 + sr * 8);
    }
    CPCOMMIT();

    const float* mp = g_mean + a * 160;
    const float* ip = g_istd + a * 160;
    size_t sbo = (size_t)a * Bsz * 128, abo = (size_t)a * Bsz * 32;
    const __half* Bp = Benc + (size_t)a * 128 * 320;

    float4 av[2];
    auto loadA = [&](int c) {
        #pragma unroll
        for (int i = 0; i < 2; i++) {
            int p = tid + i * 256;
            int row = p >> 2, kq = p & 3;
            int k = c * 16 + kq * 4;
            float4 v;
            if (k < 128) v = *(const float4*)(states + sbo + (size_t)(m0 + row) * 128 + k);
            else         v = *(const float4*)(actions + abo + (size_t)(m0 + row) * 32 + (k - 128));
            v.x = (v.x - mp[k    ]) * ip[k    ];
            v.y = (v.y - mp[k + 1]) * ip[k + 1];
            v.z = (v.z - mp[k + 2]) * ip[k + 2];
            v.w = (v.w - mp[k + 3]) * ip[k + 3];
            av[i] = v;
        }
    };
    auto stsA = [&](int buf) {
        #pragma unroll
        for (int i = 0; i < 2; i++) {
            int p = tid + i * 256;
            int row = p >> 2, kq = p & 3;
            float4 v = av[i];
            uint4 u;
            u.x = splitpk(v.x); u.y = splitpk(v.y);
            u.z = splitpk(v.z); u.w = splitpk(v.w);
            *(uint4*)(sm + buf * STAGE + row * PITCH + kq * 16) = u;
        }
    };
    auto cpB = [&](int c, int buf) {
        #pragma unroll
        for (int i = 0; i < 2; i++) {
            int s = tid + i * 256;
            int n = s >> 2, seg = s & 3;
            CP16(smu + buf * STAGE + CHNK + n * PITCH + seg * 16,
                 Bp + (size_t)n * 320 + c * 32 + seg * 8);
        }
    };

    int r = lane & 7, q = lane >> 3;
    uint32_t a_off[2], b_off[4], ws_off[4];
    #pragma unroll
    for (int mt = 0; mt < 2; mt++)
        a_off[mt] = (uint32_t)((wm * 32 + mt * 16 + (q & 1) * 8 + r) * PITCH + (q >> 1) * 16);
    #pragma unroll
    for (int np = 0; np < 4; np++) {
        uint32_t rb = (uint32_t)((wn * 64 + np * 16 + (q >> 1) * 8 + r) * PITCH + (q & 1) * 16);
        b_off[np]  = CHNK + rb;
        ws_off[np] = WSOFF + rb;
    }

    float acc[2][8][4];
    #pragma unroll
    for (int mt = 0; mt < 2; mt++)
        #pragma unroll
        for (int nt = 0; nt < 8; nt++)
            #pragma unroll
            for (int i = 0; i < 4; i++) acc[mt][nt][i] = 0.f;

    loadA(0); cpB(0, 0); CPCOMMIT();
    const int nch = 10;
    for (int c = 0; c < nch; c++) {
        int buf = c & 1;
        if (c + 1 < nch) { cpB(c + 1, buf ^ 1); CPCOMMIT(); }
        stsA(buf);
        if (c + 1 < nch) { loadA(c + 1); CPWAIT1(); }
        else             { CPWAIT0(); }
        __syncthreads();
        uint32_t bb = smu + buf * STAGE;
        #pragma unroll
        for (int ks = 0; ks < 2; ks++) {
            uint32_t af[2][4], bf[4][4];
            #pragma unroll
            for (int mt = 0; mt < 2; mt++) ldsm4(af[mt], bb + a_off[mt] + ks * 32);
            #pragma unroll
            for (int np = 0; np < 4; np++) ldsm4(bf[np], bb + b_off[np] + ks * 32);
            #pragma unroll
            for (int mt = 0; mt < 2; mt++)
                #pragma unroll
                for (int nt = 0; nt < 8; nt++)
                    mma16816(acc[mt][nt], af[mt], &bf[nt >> 1][(nt & 1) * 2]);
        }
        __syncthreads();
    }

    int g = lane >> 2, tig = lane & 3;

    // epilogue: write pairs + fp16 tile into stage region (now free)
    #pragma unroll
    for (int mt = 0; mt < 2; mt++) {
        int row = wm * 32 + mt * 16 + g;
        #pragma unroll
        for (int nt = 0; nt < 8; nt++) {
            int col = wn * 64 + nt * 8 + 2 * tig;
            float b0 = enc_b[a * 128 + col], b1 = enc_b[a * 128 + col + 1];
            float v0 = lrelu(acc[mt][nt][0] + b0), v1 = lrelu(acc[mt][nt][1] + b1);
            float v2 = lrelu(acc[mt][nt][2] + b0), v3 = lrelu(acc[mt][nt][3] + b1);
            uint2 u0; u0.x = splitpk(v0); u0.y = splitpk(v1);
            uint2 u1; u1.x = splitpk(v2); u1.y = splitpk(v3);
            *(uint2*)(saout + ((size_t)a * Bsz + m0 + row) * 128 + col) = u0;
            *(uint2*)(saout + ((size_t)a * Bsz + m0 + row + 8) * 128 + col) = u1;
            uint32_t tadr = (uint32_t)((col >> 5) * CHNK + row * PITCH + (col & 31) * 2);
            *(__half2*)(sm + tadr)             = __floats2half2_rn(v0, v1);
            *(__half2*)(sm + tadr + 8 * PITCH) = __floats2half2_rn(v2, v3);
        }
    }
    __syncthreads();

    // phase 2: sels = tile @ Ws
    float a2[2][8][4];
    #pragma unroll
    for (int mt = 0; mt < 2; mt++)
        #pragma unroll
        for (int nt = 0; nt < 8; nt++)
            #pragma unroll
            for (int i = 0; i < 4; i++) a2[mt][nt][i] = 0.f;
    #pragma unroll
    for (int ks = 0; ks < 8; ks++) {
        uint32_t coff = (uint32_t)((ks >> 1) * CHNK + (ks & 1) * 32);
        uint32_t af[2][4], bf[4][4];
        #pragma unroll
        for (int mt = 0; mt < 2; mt++) ldsm4(af[mt], smu + a_off[mt] + coff);
        #pragma unroll
        for (int np = 0; np < 4; np++) ldsm4(bf[np], smu + ws_off[np] + coff);
        #pragma unroll
        for (int mt = 0; mt < 2; mt++)
            #pragma unroll
            for (int nt = 0; nt < 8; nt++)
                mma16816(a2[mt][nt], af[mt], &bf[nt >> 1][(nt & 1) * 2]);
    }
    #pragma unroll
    for (int mt = 0; mt < 2; mt++) {
        int m = m0 + wm * 32 + mt * 16 + g;
        #pragma unroll
        for (int nt = 0; nt < 8; nt++) {
            int col = wn * 64 + nt * 8 + 2 * tig;
            *(__half2*)(selsout + ((size_t)a * Bsz + m) * 128 + col) =
                __floats2half2_rn(a2[mt][nt][0], a2[mt][nt][1]);
            *(__half2*)(selsout + ((size_t)a * Bsz + m + 8) * 128 + col) =
                __floats2half2_rn(a2[mt][nt][2], a2[mt][nt][3]);
        }
    }
}

// ---------------- fused a_enc + keys + vals ----------------
// Phase 1: aenc = lrelu(BN(actions) @ aenc_w + aenc_b) -> fp16 tile only (smem)
// Phase 2: keys = tile @ Wk ; vals = lrelu(tile @ Wv + val_b)  (B streamed)
#define BSOFF 40960
__global__ __launch_bounds__(256, 2) void aenc_kv_k(
    const float* __restrict__ actions,
    const __half* __restrict__ Baenc, const float* __restrict__ aenc_b,
    const __half* __restrict__ Wkp, const __half* __restrict__ Wvp,
    const float* __restrict__ valb,
    __half* __restrict__ keysh, __half* __restrict__ valsh) {

    extern __shared__ __align__(16) char sm[];
    uint32_t smu = smem_u32(sm);
    int tid = threadIdx.x, lane = tid & 31, wid = tid >> 5;
    int wm = wid & 3, wn = wid >> 2;
    int a = blockIdx.z, m0 = blockIdx.x * 128;

    const float* mp = g_mean + a * 160;
    const float* ip = g_istd + a * 160;
    size_t abo = (size_t)a * Bsz * 32;
    const __half* Bp = Baenc + (size_t)a * 128 * 64;

    // prefetch first streamed B2 chunk (Wk chunk 0) into stream region
    #pragma unroll
    for (int i = 0; i < 2; i++) {
        int s = tid + i * 256;
        int n = s >> 2, seg = s & 3;
        CP16(smu + BSOFF + n * PITCH + seg * 16, Wkp + (size_t)n * 128 + seg * 8);
    }
    CPCOMMIT();

    float4 av[2];
    auto loadA = [&](int c) {
        #pragma unroll
        for (int i = 0; i < 2; i++) {
            int p = tid + i * 256;
            int row = p >> 2, kq = p & 3;
            int k = c * 16 + kq * 4;
            float4 v = *(const float4*)(actions + abo + (size_t)(m0 + row) * 32 + k);
            v.x = (v.x - mp[128 + k]) * ip[128 + k];
            v.y = (v.y - mp[129 + k]) * ip[129 + k];
            v.z = (v.z - mp[130 + k]) * ip[130 + k];
            v.w = (v.w - mp[131 + k]) * ip[131 + k];
            av[i] = v;
        }
    };
    auto stsA = [&](int buf) {
        #pragma unroll
        for (int i = 0; i < 2; i++) {
            int p = tid + i * 256;
            int row = p >> 2, kq = p & 3;
            float4 v = av[i];
            uint4 u;
            u.x = splitpk(v.x); u.y = splitpk(v.y);
            u.z = splitpk(v.z); u.w = splitpk(v.w);
            *(uint4*)(sm + buf * STAGE + row * PITCH + kq * 16) = u;
        }
    };
    auto cpB = [&](int c, int buf) {
        #pragma unroll
        for (int i = 0; i < 2; i++) {
            int s = tid + i * 256;
            int n = s >> 2, seg = s & 3;
            CP16(smu + buf * STAGE + CHNK + n * PITCH + seg * 16,
                 Bp + (size_t)n * 64 + c * 32 + seg * 8);
        }
    };
    auto cpB2 = [&](int c, int buf) {   // c in 0..7: Wk chunks 0..3, Wv chunks 0..3
        const __half* src = (c < 4) ? Wkp : Wvp;
        int cc = c & 3;
        #pragma unroll
        for (int i = 0; i < 2; i++) {
            int s = tid + i * 256;
            int n = s >> 2, seg = s & 3;
            CP16(smu + BSOFF + buf * CHNK + n * PITCH + seg * 16,
                 src + (size_t)n * 128 + cc * 32 + seg * 8);
        }
    };

    int r = lane & 7, q = lane >> 3;
    uint32_t a_off[2], b_off[4], bs_off[4];
    #pragma unroll
    for (int mt = 0; mt < 2; mt++)
        a_off[mt] = (uint32_t)((wm * 32 + mt * 16 + (q & 1) * 8 + r) * PITCH + (q >> 1) * 16);
    #pragma unroll
    for (int np = 0; np < 4; np++) {
        uint32_t rb = (uint32_t)((wn * 64 + np * 16 + (q >> 1) * 8 + r) * PITCH + (q & 1) * 16);
        b_off[np]  = CHNK + rb;
        bs_off[np] = BSOFF + rb;
    }

    float acc[2][8][4];
    #pragma unroll
    for (int mt = 0; mt < 2; mt++)
        #pragma unroll
        for (int nt = 0; nt < 8; nt++)
            #pragma unroll
            for (int i = 0; i < 4; i++) acc[mt][nt][i] = 0.f;

    loadA(0); cpB(0, 0); CPCOMMIT();
    for (int c = 0; c < 2; c++) {
        int buf = c & 1;
        if (c == 0) { cpB(1, 1); CPCOMMIT(); }
        stsA(buf);
        if (c == 0) { loadA(1); CPWAIT1(); }
        else        { CPWAIT0(); }
        __syncthreads();
        uint32_t bb = smu + buf * STAGE;
        #pragma unroll
        for (int ks = 0; ks < 2; ks++) {
            uint32_t af[2][4], bf[4][4];
            #pragma unroll
            for (int mt = 0; mt < 2; mt++) ldsm4(af[mt], bb + a_off[mt] + ks * 32);
            #pragma unroll
            for (int np = 0; np < 4; np++) ldsm4(bf[np], bb + b_off[np] + ks * 32);
            #pragma unroll
            for (int mt = 0; mt < 2; mt++)
                #pragma unroll
                for (int nt = 0; nt < 8; nt++)
                    mma16816(acc[mt][nt], af[mt], &bf[nt >> 1][(nt & 1) * 2]);
        }
        __syncthreads();
    }

    int g = lane >> 2, tig = lane & 3;

    // epilogue: aenc tile (fp16) into stage region
    #pragma unroll
    for (int mt = 0; mt < 2; mt++) {
        int row = wm * 32 + mt * 16 + g;
        #pragma unroll
        for (int nt = 0; nt < 8; nt++) {
            int col = wn * 64 + nt * 8 + 2 * tig;
            float b0 = aenc_b[a * 128 + col], b1 = aenc_b[a * 128 + col + 1];
            float v0 = lrelu(acc[mt][nt][0] + b0), v1 = lrelu(acc[mt][nt][1] + b1);
            float v2 = lrelu(acc[mt][nt][2] + b0), v3 = lrelu(acc[mt][nt][3] + b1);
            uint32_t tadr = (uint32_t)((col >> 5) * CHNK + row * PITCH + (col & 31) * 2);
            *(__half2*)(sm + tadr)             = __floats2half2_rn(v0, v1);
            *(__half2*)(sm + tadr + 8 * PITCH) = __floats2half2_rn(v2, v3);
            acc[mt][nt][0] = 0.f; acc[mt][nt][1] = 0.f;
            acc[mt][nt][2] = 0.f; acc[mt][nt][3] = 0.f;
        }
    }
    __syncthreads();

    // phase 2: stream Wk/Wv, 8 chunks x 2 ksteps
    for (int c = 0; c < 8; c++) {
        int buf = c & 1;
        if (c + 1 < 8) { cpB2(c + 1, buf ^ 1); CPCOMMIT(); CPWAIT1(); }
        else           { CPWAIT0(); }
        __syncthreads();
        #pragma unroll
        for (int ks = 0; ks < 2; ks++) {
            uint32_t coffA = (uint32_t)((c & 3) * CHNK + ks * 32);
            uint32_t af[2][4], bf[4][4];
            #pragma unroll
            for (int mt = 0; mt < 2; mt++) ldsm4(af[mt], smu + a_off[mt] + coffA);
            #pragma unroll
            for (int np = 0; np < 4; np++) ldsm4(bf[np], smu + bs_off[np] + buf * CHNK + ks * 32);
            #pragma unroll
            for (int mt = 0; mt < 2; mt++)
                #pragma unroll
                for (int nt = 0; nt < 8; nt++)
                    mma16816(acc[mt][nt], af[mt], &bf[nt >> 1][(nt & 1) * 2]);
        }
        __syncthreads();

        if (c == 3 || c == 7) {
            bool isv = (c == 7);
            __half* outp = isv ? valsh : keysh;
            #pragma unroll
            for (int mt = 0; mt < 2; mt++) {
                int m = m0 + wm * 32 + mt * 16 + g;
                #pragma unroll
                for (int nt = 0; nt < 8; nt++) {
                    int col = wn * 64 + nt * 8 + 2 * tig;
                    float v0 = acc[mt][nt][0], v1 = acc[mt][nt][1];
                    float v2 = acc[mt][nt][2], v3 = acc[mt][nt][3];
                    if (isv) {
                        float b0 = valb[col], b1 = valb[col + 1];
                        v0 = lrelu(v0 + b0); v1 = lrelu(v1 + b1);
                        v2 = lrelu(v2 + b0); v3 = lrelu(v3 + b1);
                    }
                    *(__half2*)(outp + ((size_t)a * Bsz + m) * 128 + col) = __floats2half2_rn(v0, v1);
                    *(__half2*)(outp + ((size_t)a * Bsz + m + 8) * 128 + col) = __floats2half2_rn(v2, v3);
                    acc[mt][nt][0] = 0.f; acc[mt][nt][1] = 0.f;
                    acc[mt][nt][2] = 0.f; acc[mt][nt][3] = 0.f;
                }
            }
        }
    }
}

// ---------------- c1 + q fused, mixed K'=384 (sa dup pairs + att single) ----------------
__global__ __launch_bounds__(256, 2) void c1q_k(
    const uint32_t* __restrict__ sap, const __half* __restrict__ att,
    const __half* __restrict__ Bc1, const float* __restrict__ c1_b,
    const float* __restrict__ c2w, const float* __restrict__ c2b,
    float* __restrict__ qout) {

    __shared__ __align__(16) char sm[2][STAGE];
    uint32_t smu = smem_u32(sm);
    int tid = threadIdx.x, lane = tid & 31, wid = tid >> 5;
    int wm = wid & 3, wn = wid >> 2;
    int a = blockIdx.z, m0 = blockIdx.x * 128;

    const char* Ap = (const char*)(sap + (size_t)a * Bsz * 128);
    const char* Atp = (const char*)(att + (size_t)a * Bsz * 128);
    const __half* Bp = Bc1 + (size_t)a * 128 * 384;

    auto cpA = [&](int c, int buf) {
        #pragma unroll
        for (int i = 0; i < 2; i++) {
            int p = tid + i * 256;
            int row = p >> 2, seg = p & 3;
            const char* g;
            if (c < 8) g = Ap + (size_t)(m0 + row) * 512 + c * 64 + seg * 16;
            else       g = Atp + (size_t)(m0 + row) * 256 + (c - 8) * 64 + seg * 16;
            CP16(smu + buf * STAGE + row * PITCH + seg * 16, g);
        }
    };
    auto cpB = [&](int c, int buf) {
        #pragma unroll
        for (int i = 0; i < 2; i++) {
            int s = tid + i * 256;
            int n = s >> 2, seg = s & 3;
            CP16(smu + buf * STAGE + CHNK + n * PITCH + seg * 16,
                 Bp + (size_t)n * 384 + c * 32 + seg * 8);
        }
    };

    int r = lane & 7, q = lane >> 3;
    uint32_t a_off[2], b_off[4];
    #pragma unroll
    for (int mt = 0; mt < 2; mt++)
        a_off[mt] = (uint32_t)((wm * 32 + mt * 16 + (q & 1) * 8 + r) * PITCH + (q >> 1) * 16);
    #pragma unroll
    for (int np = 0; np < 4; np++)
        b_off[np] = (uint32_t)(CHNK + (wn * 64 + np * 16 + (q >> 1) * 8 + r) * PITCH + (q & 1) * 16);

    float acc[2][8][4];
    #pragma unroll
    for (int mt = 0; mt < 2; mt++)
        #pragma unroll
        for (int nt = 0; nt < 8; nt++)
            #pragma unroll
            for (int i = 0; i < 4; i++) acc[mt][nt][i] = 0.f;

    cpA(0, 0); cpB(0, 0); CPCOMMIT();
    const int nch = 12;
    for (int c = 0; c < nch; c++) {
        int buf = c & 1;
        if (c + 1 < nch) { cpA(c + 1, buf ^ 1); cpB(c + 1, buf ^ 1); CPCOMMIT(); CPWAIT1(); }
        else             { CPWAIT0(); }
        __syncthreads();
        uint32_t bb = smu + buf * STAGE;
        #pragma unroll
        for (int ks = 0; ks < 2; ks++) {
            uint32_t af[2][4], bf[4][4];
            #pragma unroll
            for (int mt = 0; mt < 2; mt++) ldsm4(af[mt], bb + a_off[mt] + ks * 32);
            #pragma unroll
            for (int np = 0; np < 4; np++) ldsm4(bf[np], bb + b_off[np] + ks * 32);
            #pragma unroll
            for (int mt = 0; mt < 2; mt++)
                #pragma unroll
                for (int nt = 0; nt < 8; nt++)
                    mma16816(acc[mt][nt], af[mt], &bf[nt >> 1][(nt & 1) * 2]);
        }
        __syncthreads();
    }

    int g = lane >> 2, tig = lane & 3;
    float qp[4] = {0.f, 0.f, 0.f, 0.f};
    #pragma unroll
    for (int mt = 0; mt < 2; mt++)
        #pragma unroll
        for (int nt = 0; nt < 8; nt++) {
            int col = wn * 64 + nt * 8 + 2 * tig;
            float b0 = c1_b[a * 128 + col], b1 = c1_b[a * 128 + col + 1];
            float w0 = c2w[a * 128 + col], w1 = c2w[a * 128 + col + 1];
            qp[mt * 2]     += lrelu(acc[mt][nt][0] + b0) * w0 + lrelu(acc[mt][nt][1] + b1) * w1;
            qp[mt * 2 + 1] += lrelu(acc[mt][nt][2] + b0) * w0 + lrelu(acc[mt][nt][3] + b1) * w1;
        }
    #pragma unroll
    for (int j = 0; j < 4; j++) {
        qp[j] += __shfl_xor_sync(0xffffffffu, qp[j], 1);
        qp[j] += __shfl_xor_sync(0xffffffffu, qp[j], 2);
    }
    __syncthreads();
    float* qsm = (float*)sm;
    if (tig == 0) {
        #pragma unroll
        for (int j = 0; j < 4; j++) {
            int rl = wm * 32 + (j >> 1) * 16 + (j & 1) * 8 + g;
            qsm[rl * 2 + wn] = qp[j];
        }
    }
    __syncthreads();
    if (tid < 128)
        qout[(size_t)a * Bsz + m0 + tid] = qsm[tid * 2] + qsm[tid * 2 + 1] + c2b[a];
}

// ---------------- attention: 16 batch elts x 8 agents per block, fp16 in/out ----
#define APITCH 36
__global__ __launch_bounds__(128) void attn_k() {
    __shared__ __half sS[128 * APITCH];
    __shared__ __half sK[128 * APITCH];
    int t = threadIdx.x;
    int b0 = blockIdx.x * 16;
    int bl = t >> 3, iq = t & 7;

    for (int kh = 0; kh < 4; kh++) {
        __syncthreads();
        {
            int lbl = t >> 3, ag = t & 7;
            size_t off = ((size_t)ag * Bsz + b0 + lbl) * 128 + kh * 32;
            const uint2* ps = (const uint2*)(g_selsh + off);
            const uint2* pk = (const uint2*)(g_keysh + off);
            uint2* ds = (uint2*)(sS + (lbl * 8 + ag) * APITCH);
            uint2* dk = (uint2*)(sK + (lbl * 8 + ag) * APITCH);
            #pragma unroll
            for (int j = 0; j < 8; j++) { ds[j] = ps[j]; dk[j] = pk[j]; }
        }
        __syncthreads();

        float sv[32];
        {
            const __half2* p = (const __half2*)(sS + (bl * 8 + iq) * APITCH);
            #pragma unroll
            for (int d = 0; d < 16; d++) {
                float2 f = __half22float2(p[d]);
                sv[2 * d] = f.x; sv[2 * d + 1] = f.y;
            }
        }
        float pj[8];
        #pragma unroll
        for (int j = 0; j < 8; j++) {
            const __half2* p = (const __half2*)(sK + (bl * 8 + j) * APITCH);
            float acc = 0.f;
            #pragma unroll
            for (int d = 0; d < 16; d++) {
                float2 f = __half22float2(p[d]);
                acc += sv[2 * d] * f.x + sv[2 * d + 1] * f.y;
            }
            pj[j] = acc * 0.17677669529663687f;
        }
        float mx = -1e30f;
        #pragma unroll
        for (int j = 0; j < 8; j++) if (j != iq) mx = fmaxf(mx, pj[j]);
        float sum = 0.f;
        #pragma unroll
        for (int j = 0; j < 8; j++) {
            pj[j] = (j == iq) ? 0.f : __expf(pj[j] - mx);
            sum += pj[j];
        }
        float inv = 1.f / sum;

        __syncthreads();
        {
            int lbl = t >> 3, ag = t & 7;
            size_t off = ((size_t)ag * Bsz + b0 + lbl) * 128 + kh * 32;
            const uint2* pv = (const uint2*)(g_valsh + off);
            uint2* ds = (uint2*)(sS + (lbl * 8 + ag) * APITCH);
            #pragma unroll
            for (int j = 0; j < 8; j++) ds[j] = pv[j];
        }
        __syncthreads();

        float ov[32];
        #pragma unroll
        for (int d = 0; d < 32; d++) ov[d] = 0.f;
        #pragma unroll
        for (int j = 0; j < 8; j++) {
            float w = pj[j] * inv;
            const __half2* p = (const __half2*)(sS + (bl * 8 + j) * APITCH);
            #pragma unroll
            for (int d = 0; d < 16; d++) {
                float2 f = __half22float2(p[d]);
                ov[2 * d]     += w * f.x;
                ov[2 * d + 1] += w * f.y;
            }
        }
        __half* dst = g_atth + ((size_t)iq * Bsz + b0 + bl) * 128 + kh * 32;
        #pragma unroll
        for (int d4 = 0; d4 < 4; d4++) {
            __half2 h0 = __floats2half2_rn(ov[d4 * 8 + 0], ov[d4 * 8 + 1]);
            __half2 h1 = __floats2half2_rn(ov[d4 * 8 + 2], ov[d4 * 8 + 3]);
            __half2 h2 = __floats2half2_rn(ov[d4 * 8 + 4], ov[d4 * 8 + 5]);
            __half2 h3 = __floats2half2_rn(ov[d4 * 8 + 6], ov[d4 * 8 + 7]);
            uint4 u;
            u.x = *(uint32_t*)&h0; u.y = *(uint32_t*)&h1;
            u.z = *(uint32_t*)&h2; u.w = *(uint32_t*)&h3;
            *(uint4*)(dst + d4 * 8) = u;
        }
    }
}

// ---------------- launch ----------------
extern "C" void kernel_launch(void* const* d_in, const int* in_sizes, int n_in,
                              void* d_out, int out_size) {
    const float* states = (const float*)d_in[0];
    const float* actions= (const float*)d_in[1];
    const float* enc_w  = (const float*)d_in[2];
    const float* enc_b  = (const float*)d_in[3];
    const float* aenc_w = (const float*)d_in[4];
    const float* aenc_b = (const float*)d_in[5];
    const float* key_w  = (const float*)d_in[6];
    const float* sel_w  = (const float*)d_in[7];
    const float* val_w  = (const float*)d_in[8];
    const float* val_b  = (const float*)d_in[9];
    const float* c1_w   = (const float*)d_in[10];
    const float* c1_b   = (const float*)d_in[11];
    const float* c2_w   = (const float*)d_in[12];
    const float* c2_b   = (const float*)d_in[13];
    float* out = (float*)d_out;

    void *p_sa, *p_keysh, *p_selsh, *p_valsh, *p_atth;
    void *p_Benc, *p_Baenc, *p_Bc1, *p_Wkp, *p_Wsp, *p_Wvp;
    cudaGetSymbolAddress(&p_sa,   g_sa);
    cudaGetSymbolAddress(&p_keysh,g_keysh);
    cudaGetSymbolAddress(&p_selsh,g_selsh);
    cudaGetSymbolAddress(&p_valsh,g_valsh);
    cudaGetSymbolAddress(&p_atth, g_atth);
    cudaGetSymbolAddress(&p_Benc, g_Benc);
    cudaGetSymbolAddress(&p_Baenc,g_Baenc);
    cudaGetSymbolAddress(&p_Bc1,  g_Bc1);
    cudaGetSymbolAddress(&p_Wkp,  g_Wkp);
    cudaGetSymbolAddress(&p_Wsp,  g_Wsp);
    cudaGetSymbolAddress(&p_Wvp,  g_Wvp);

    cudaFuncSetAttribute(sa_sels_k, cudaFuncAttributeMaxDynamicSharedMemorySize, 81920);
    cudaFuncSetAttribute(aenc_kv_k, cudaFuncAttributeMaxDynamicSharedMemorySize, 61440);

    bn_partial_k<<<dim3(32, 8), 320>>>(states, actions);
    bn_final_k<<<8, 160>>>();
    pack_w<<<dim3(10, 8), 256>>>(enc_w,  (__half*)p_Benc, 160, 0, 1, 320, 0);
    pack_w<<<dim3(2, 8),  256>>>(aenc_w, (__half*)p_Baenc, 32, 0, 1, 64, 0);
    pack_w<<<dim3(8, 8),  256>>>(c1_w,              (__half*)p_Bc1, 256, 0, 1, 384, 0);
    pack_w<<<dim3(8, 8),  256>>>(c1_w + 128 * 128,  (__half*)p_Bc1, 256, 0, 0, 384, 256);
    pack_w<<<dim3(8, 1),  256>>>(key_w,  (__half*)p_Wkp, 128, 1, 0, 128, 0);
    pack_w<<<dim3(8, 1),  256>>>(sel_w,  (__half*)p_Wsp, 128, 1, 0, 128, 0);
    pack_w<<<dim3(8, 1),  256>>>(val_w,  (__half*)p_Wvp, 128, 1, 0, 128, 0);

    dim3 gg(256, 1, 8);
    sa_sels_k<<<gg, 256, 81920>>>(states, actions,
                                  (const __half*)p_Benc, enc_b,
                                  (const __half*)p_Wsp,
                                  (uint32_t*)p_sa, (__half*)p_selsh);
    aenc_kv_k<<<gg, 256, 61440>>>(actions,
                                  (const __half*)p_Baenc, aenc_b,
                                  (const __half*)p_Wkp, (const __half*)p_Wvp,
                                  val_b, (__half*)p_keysh, (__half*)p_valsh);
    attn_k<<<Bsz / 16, 128>>>();
    c1q_k<<<gg, 256>>>((const uint32_t*)p_sa, (const __half*)p_atth,
                       (const __half*)p_Bc1, c1_b, c2_w, c2_b, out);
}

// round 8
// speedup vs baseline: 1.6027x; 1.1498x over previous
#include <cuda_runtime.h>
#include <cuda_fp16.h>
#include <cstdint>
#include <cstddef>

#define A_   8
#define Bsz  32768
#define EPSB 1e-5f

// ---------------- static scratch ----------------
__device__ float g_part[8 * 32 * 160 * 2];
__device__ float g_mean[8 * 160];
__device__ float g_istd[8 * 160];
// plain fp16 tensors
__device__ __align__(128) __half g_sah  [(size_t)A_ * Bsz * 128];
__device__ __align__(128) __half g_keysh[(size_t)A_ * Bsz * 128];
__device__ __align__(128) __half g_selsh[(size_t)A_ * Bsz * 128];
__device__ __align__(128) __half g_valsh[(size_t)A_ * Bsz * 128];
__device__ __align__(128) __half g_atth [(size_t)A_ * Bsz * 128];
// nodup fp16 weights [agent][n][K]
__device__ __align__(128) __half g_Benc [(size_t)8 * 128 * 160];
__device__ __align__(128) __half g_Baenc[(size_t)8 * 128 * 32];
__device__ __align__(128) __half g_Bc1  [(size_t)8 * 128 * 256];
__device__ __align__(128) __half g_Wkp[128 * 128];
__device__ __align__(128) __half g_Wsp[128 * 128];
__device__ __align__(128) __half g_Wvp[128 * 128];

__device__ __forceinline__ float lrelu(float x) { return fmaxf(x, 0.01f * x); }
__device__ __forceinline__ uint32_t smem_u32(const void* p) {
    uint32_t a;
    asm("{ .reg .u64 t; cvta.to.shared.u64 t, %1; cvt.u32.u64 %0, t; }" : "=r"(a) : "l"(p));
    return a;
}
__device__ __forceinline__ void ldsm4(uint32_t* r, uint32_t addr) {
    asm volatile("ldmatrix.sync.aligned.m8n8.x4.shared.b16 {%0,%1,%2,%3}, [%4];"
        : "=r"(r[0]), "=r"(r[1]), "=r"(r[2]), "=r"(r[3]) : "r"(addr));
}
__device__ __forceinline__ void mma16816(float* d, const uint32_t* a, const uint32_t* b) {
    asm volatile("mma.sync.aligned.m16n8k16.row.col.f32.f16.f16.f32 "
        "{%0,%1,%2,%3}, {%4,%5,%6,%7}, {%8,%9}, {%0,%1,%2,%3};"
        : "+f"(d[0]), "+f"(d[1]), "+f"(d[2]), "+f"(d[3])
        : "r"(a[0]), "r"(a[1]), "r"(a[2]), "r"(a[3]), "r"(b[0]), "r"(b[1]));
}
#define CP16(s, g) asm volatile("cp.async.cg.shared.global [%0], [%1], 16;" :: "r"(s), "l"(g))
#define CPCOMMIT() asm volatile("cp.async.commit_group;" ::: "memory")
#define CPWAIT1()  asm volatile("cp.async.wait_group 1;" ::: "memory")
#define CPWAIT0()  asm volatile("cp.async.wait_group 0;" ::: "memory")

__device__ __forceinline__ uint32_t pkh2(__half a, __half b) {
    __half2 h = __halves2half2(a, b);
    return *(uint32_t*)&h;
}

#define PITCH 80
#define STAGE 20480
#define CHNK  10240

// ---------------- BatchNorm stats ----------------
__global__ void bn_partial_k(const float* __restrict__ states,
                             const float* __restrict__ actions) {
    int a = blockIdx.y, chunk = blockIdx.x;
    int t = threadIdx.x;
    int f = t % 160, r0 = t / 160;
    size_t sb = (size_t)a * Bsz * 128, ab = (size_t)a * Bsz * 32;
    int row0 = chunk * 1024;
    float s = 0.f, s2 = 0.f;
    if (f < 128) {
        const float* p = states + sb + (size_t)(row0 + r0) * 128 + f;
        #pragma unroll 4
        for (int r = 0; r < 512; r++) { float v = *p; p += 256; s += v; s2 += v * v; }
    } else {
        const float* p = actions + ab + (size_t)(row0 + r0) * 32 + (f - 128);
        #pragma unroll 4
        for (int r = 0; r < 512; r++) { float v = *p; p += 64; s += v; s2 += v * v; }
    }
    __shared__ float sh[640];
    sh[t] = s; sh[320 + t] = s2;
    __syncthreads();
    if (t < 160) {
        float ss = sh[t] + sh[t + 160];
        float qq = sh[320 + t] + sh[320 + t + 160];
        int o = ((a * 32 + chunk) * 160 + t) * 2;
        g_part[o] = ss; g_part[o + 1] = qq;
    }
}

__global__ void bn_final_k() {
    int a = blockIdx.x, f = threadIdx.x;
    float s = 0.f, s2 = 0.f;
    for (int c = 0; c < 32; c++) {
        int o = ((a * 32 + c) * 160 + f) * 2;
        s += g_part[o]; s2 += g_part[o + 1];
    }
    float m = s * (1.f / 32768.f);
    float v = s2 * (1.f / 32768.f) - m * m;
    g_mean[a * 160 + f] = m;
    g_istd[a * 160 + f] = rsqrtf(v + EPSB);
}

// ---------------- weight pack: transpose + fp16, nodup, strided dst ----------
// mode 0: src [a][k][n=128]    mode 1: heads src [(n>>5)][k][n&31]
__global__ void pack_w(const float* __restrict__ src, __half* __restrict__ dst,
                       int Ksrc, int mode, int dstStride, int dstOff) {
    __shared__ float tile[16][128];
    int a = blockIdx.y, kt = blockIdx.x, t = threadIdx.x;
    int k0 = kt * 16;
    #pragma unroll
    for (int i = 0; i < 2; i++) {
        int p = t + i * 256;
        int kk = p >> 5, n4 = (p & 31) * 4;
        float4 v;
        if (mode == 0)
            v = *(const float4*)(src + ((size_t)a * Ksrc + k0 + kk) * 128 + n4);
        else
            v = *(const float4*)(src + ((size_t)(n4 >> 5) * 128 + k0 + kk) * 32 + (n4 & 31));
        tile[kk][n4] = v.x; tile[kk][n4 + 1] = v.y;
        tile[kk][n4 + 2] = v.z; tile[kk][n4 + 3] = v.w;
    }
    __syncthreads();
    #pragma unroll
    for (int i = 0; i < 2; i++) {
        int p = t + i * 256;
        int n = p >> 2, kq = p & 3;
        __half h[4];
        #pragma unroll
        for (int j = 0; j < 4; j++)
            h[j] = __float2half_rn(tile[kq * 4 + j][n]);
        uint2 u;
        u.x = pkh2(h[0], h[1]); u.y = pkh2(h[2], h[3]);
        *(uint2*)(dst + (size_t)a * 128 * dstStride + (size_t)n * dstStride
                      + dstOff + kt * 16 + kq * 4) = u;
    }
}

// ---------------- fused sa_enc + sels (all fp16 nodup) ----------------
#define WSOFF 40960
__global__ __launch_bounds__(256, 2) void sa_sels_k(
    const float* __restrict__ states, const float* __restrict__ actions,
    const __half* __restrict__ Benc, const float* __restrict__ enc_b,
    const __half* __restrict__ Wsp,
    __half* __restrict__ saout, __half* __restrict__ selsout) {

    extern __shared__ __align__(16) char sm[];
    uint32_t smu = smem_u32(sm);
    int tid = threadIdx.x, lane = tid & 31, wid = tid >> 5;
    int wm = wid & 3, wn = wid >> 2;
    int a = blockIdx.z, m0 = blockIdx.x * 128;

    // Ws resident
    #pragma unroll
    for (int i = 0; i < 8; i++) {
        int s = tid + 256 * i;
        int n = s >> 4, sr = s & 15;
        CP16(smu + WSOFF + (sr >> 2) * CHNK + n * PITCH + (sr & 3) * 16,
             Wsp + (size_t)n * 128 + sr * 8);
    }
    CPCOMMIT();

    const float* mp = g_mean + a * 160;
    const float* ip = g_istd + a * 160;
    size_t sbo = (size_t)a * Bsz * 128, abo = (size_t)a * Bsz * 32;
    const __half* Bp = Benc + (size_t)a * 128 * 160;

    float4 av[2][2];
    auto loadA = [&](int c) {
        #pragma unroll
        for (int i = 0; i < 2; i++) {
            int p = tid + i * 256;
            int row = p >> 2, kq = p & 3;
            int k = c * 32 + kq * 8;
            #pragma unroll
            for (int h = 0; h < 2; h++) {
                int kk = k + h * 4;
                float4 v;
                if (kk < 128) v = *(const float4*)(states + sbo + (size_t)(m0 + row) * 128 + kk);
                else          v = *(const float4*)(actions + abo + (size_t)(m0 + row) * 32 + (kk - 128));
                v.x = (v.x - mp[kk    ]) * ip[kk    ];
                v.y = (v.y - mp[kk + 1]) * ip[kk + 1];
                v.z = (v.z - mp[kk + 2]) * ip[kk + 2];
                v.w = (v.w - mp[kk + 3]) * ip[kk + 3];
                av[i][h] = v;
            }
        }
    };
    auto stsA = [&](int buf) {
        #pragma unroll
        for (int i = 0; i < 2; i++) {
            int p = tid + i * 256;
            int row = p >> 2, kq = p & 3;
            uint4 u;
            u.x = pkh2(__float2half_rn(av[i][0].x), __float2half_rn(av[i][0].y));
            u.y = pkh2(__float2half_rn(av[i][0].z), __float2half_rn(av[i][0].w));
            u.z = pkh2(__float2half_rn(av[i][1].x), __float2half_rn(av[i][1].y));
            u.w = pkh2(__float2half_rn(av[i][1].z), __float2half_rn(av[i][1].w));
            *(uint4*)(sm + buf * STAGE + row * PITCH + kq * 16) = u;
        }
    };
    auto cpB = [&](int c, int buf) {
        #pragma unroll
        for (int i = 0; i < 2; i++) {
            int s = tid + i * 256;
            int n = s >> 2, seg = s & 3;
            CP16(smu + buf * STAGE + CHNK + n * PITCH + seg * 16,
                 Bp + (size_t)n * 160 + c * 32 + seg * 8);
        }
    };

    int r = lane & 7, q = lane >> 3;
    uint32_t a_off[2], b_off[4], ws_off[4];
    #pragma unroll
    for (int mt = 0; mt < 2; mt++)
        a_off[mt] = (uint32_t)((wm * 32 + mt * 16 + (q & 1) * 8 + r) * PITCH + (q >> 1) * 16);
    #pragma unroll
    for (int np = 0; np < 4; np++) {
        uint32_t rb = (uint32_t)((wn * 64 + np * 16 + (q >> 1) * 8 + r) * PITCH + (q & 1) * 16);
        b_off[np]  = CHNK + rb;
        ws_off[np] = WSOFF + rb;
    }

    float acc[2][8][4];
    #pragma unroll
    for (int mt = 0; mt < 2; mt++)
        #pragma unroll
        for (int nt = 0; nt < 8; nt++)
            #pragma unroll
            for (int i = 0; i < 4; i++) acc[mt][nt][i] = 0.f;

    loadA(0); cpB(0, 0); CPCOMMIT();
    const int nch = 5;
    for (int c = 0; c < nch; c++) {
        int buf = c & 1;
        if (c + 1 < nch) { cpB(c + 1, buf ^ 1); CPCOMMIT(); }
        stsA(buf);
        if (c + 1 < nch) { loadA(c + 1); CPWAIT1(); }
        else             { CPWAIT0(); }
        __syncthreads();
        uint32_t bb = smu + buf * STAGE;
        #pragma unroll
        for (int ks = 0; ks < 2; ks++) {
            uint32_t af[2][4], bf[4][4];
            #pragma unroll
            for (int mt = 0; mt < 2; mt++) ldsm4(af[mt], bb + a_off[mt] + ks * 32);
            #pragma unroll
            for (int np = 0; np < 4; np++) ldsm4(bf[np], bb + b_off[np] + ks * 32);
            #pragma unroll
            for (int mt = 0; mt < 2; mt++)
                #pragma unroll
                for (int nt = 0; nt < 8; nt++)
                    mma16816(acc[mt][nt], af[mt], &bf[nt >> 1][(nt & 1) * 2]);
        }
        __syncthreads();
    }

    int g = lane >> 2, tig = lane & 3;

    // epilogue: fp16 out + fp16 tile in stage region
    #pragma unroll
    for (int mt = 0; mt < 2; mt++) {
        int row = wm * 32 + mt * 16 + g;
        #pragma unroll
        for (int nt = 0; nt < 8; nt++) {
            int col = wn * 64 + nt * 8 + 2 * tig;
            float b0 = enc_b[a * 128 + col], b1 = enc_b[a * 128 + col + 1];
            float v0 = lrelu(acc[mt][nt][0] + b0), v1 = lrelu(acc[mt][nt][1] + b1);
            float v2 = lrelu(acc[mt][nt][2] + b0), v3 = lrelu(acc[mt][nt][3] + b1);
            __half2 h0 = __floats2half2_rn(v0, v1);
            __half2 h1 = __floats2half2_rn(v2, v3);
            *(__half2*)(saout + ((size_t)a * Bsz + m0 + row) * 128 + col) = h0;
            *(__half2*)(saout + ((size_t)a * Bsz + m0 + row + 8) * 128 + col) = h1;
            uint32_t tadr = (uint32_t)((col >> 5) * CHNK + row * PITCH + (col & 31) * 2);
            *(__half2*)(sm + tadr)             = h0;
            *(__half2*)(sm + tadr + 8 * PITCH) = h1;
        }
    }
    __syncthreads();

    // phase 2: sels = tile @ Ws
    float a2[2][8][4];
    #pragma unroll
    for (int mt = 0; mt < 2; mt++)
        #pragma unroll
        for (int nt = 0; nt < 8; nt++)
            #pragma unroll
            for (int i = 0; i < 4; i++) a2[mt][nt][i] = 0.f;
    #pragma unroll
    for (int ks = 0; ks < 8; ks++) {
        uint32_t coff = (uint32_t)((ks >> 1) * CHNK + (ks & 1) * 32);
        uint32_t af[2][4], bf[4][4];
        #pragma unroll
        for (int mt = 0; mt < 2; mt++) ldsm4(af[mt], smu + a_off[mt] + coff);
        #pragma unroll
        for (int np = 0; np < 4; np++) ldsm4(bf[np], smu + ws_off[np] + coff);
        #pragma unroll
        for (int mt = 0; mt < 2; mt++)
            #pragma unroll
            for (int nt = 0; nt < 8; nt++)
                mma16816(a2[mt][nt], af[mt], &bf[nt >> 1][(nt & 1) * 2]);
    }
    #pragma unroll
    for (int mt = 0; mt < 2; mt++) {
        int m = m0 + wm * 32 + mt * 16 + g;
        #pragma unroll
        for (int nt = 0; nt < 8; nt++) {
            int col = wn * 64 + nt * 8 + 2 * tig;
            *(__half2*)(selsout + ((size_t)a * Bsz + m) * 128 + col) =
                __floats2half2_rn(a2[mt][nt][0], a2[mt][nt][1]);
            *(__half2*)(selsout + ((size_t)a * Bsz + m + 8) * 128 + col) =
                __floats2half2_rn(a2[mt][nt][2], a2[mt][nt][3]);
        }
    }
}

// ---------------- fused a_enc + keys + vals ----------------
#define BSOFF 40960
__global__ __launch_bounds__(256, 2) void aenc_kv_k(
    const float* __restrict__ actions,
    const __half* __restrict__ Baenc, const float* __restrict__ aenc_b,
    const __half* __restrict__ Wkp, const __half* __restrict__ Wvp,
    const float* __restrict__ valb,
    __half* __restrict__ keysh, __half* __restrict__ valsh) {

    extern __shared__ __align__(16) char sm[];
    uint32_t smu = smem_u32(sm);
    int tid = threadIdx.x, lane = tid & 31, wid = tid >> 5;
    int wm = wid & 3, wn = wid >> 2;
    int a = blockIdx.z, m0 = blockIdx.x * 128;

    const float* mp = g_mean + a * 160;
    const float* ip = g_istd + a * 160;
    size_t abo = (size_t)a * Bsz * 32;
    const __half* Bp = Baenc + (size_t)a * 128 * 32;

    // prefetch Wk chunk 0 into stream region
    #pragma unroll
    for (int i = 0; i < 2; i++) {
        int s = tid + i * 256;
        int n = s >> 2, seg = s & 3;
        CP16(smu + BSOFF + n * PITCH + seg * 16, Wkp + (size_t)n * 128 + seg * 8);
    }
    CPCOMMIT();

    // A: one chunk of K=32 (entire actions row)
    float4 av[2][2];
    #pragma unroll
    for (int i = 0; i < 2; i++) {
        int p = tid + i * 256;
        int row = p >> 2, kq = p & 3;
        #pragma unroll
        for (int h = 0; h < 2; h++) {
            int kk = kq * 8 + h * 4;
            float4 v = *(const float4*)(actions + abo + (size_t)(m0 + row) * 32 + kk);
            v.x = (v.x - mp[128 + kk]) * ip[128 + kk];
            v.y = (v.y - mp[129 + kk]) * ip[129 + kk];
            v.z = (v.z - mp[130 + kk]) * ip[130 + kk];
            v.w = (v.w - mp[131 + kk]) * ip[131 + kk];
            av[i][h] = v;
        }
    }
    // B: one chunk (K=32 halves = 64B/row)
    #pragma unroll
    for (int i = 0; i < 2; i++) {
        int s = tid + i * 256;
        int n = s >> 2, seg = s & 3;
        CP16(smu + CHNK + n * PITCH + seg * 16, Bp + (size_t)n * 32 + seg * 8);
    }
    CPCOMMIT();
    #pragma unroll
    for (int i = 0; i < 2; i++) {
        int p = tid + i * 256;
        int row = p >> 2, kq = p & 3;
        uint4 u;
        u.x = pkh2(__float2half_rn(av[i][0].x), __float2half_rn(av[i][0].y));
        u.y = pkh2(__float2half_rn(av[i][0].z), __float2half_rn(av[i][0].w));
        u.z = pkh2(__float2half_rn(av[i][1].x), __float2half_rn(av[i][1].y));
        u.w = pkh2(__float2half_rn(av[i][1].z), __float2half_rn(av[i][1].w));
        *(uint4*)(sm + row * PITCH + kq * 16) = u;
    }
    CPWAIT0();
    __syncthreads();

    int r = lane & 7, q = lane >> 3;
    uint32_t a_off[2], b_off[4], bs_off[4];
    #pragma unroll
    for (int mt = 0; mt < 2; mt++)
        a_off[mt] = (uint32_t)((wm * 32 + mt * 16 + (q & 1) * 8 + r) * PITCH + (q >> 1) * 16);
    #pragma unroll
    for (int np = 0; np < 4; np++) {
        uint32_t rb = (uint32_t)((wn * 64 + np * 16 + (q >> 1) * 8 + r) * PITCH + (q & 1) * 16);
        b_off[np]  = CHNK + rb;
        bs_off[np] = BSOFF + rb;
    }

    float acc[2][8][4];
    #pragma unroll
    for (int mt = 0; mt < 2; mt++)
        #pragma unroll
        for (int nt = 0; nt < 8; nt++)
            #pragma unroll
            for (int i = 0; i < 4; i++) acc[mt][nt][i] = 0.f;

    // mainloop: single chunk, 2 ksteps
    #pragma unroll
    for (int ks = 0; ks < 2; ks++) {
        uint32_t af[2][4], bf[4][4];
        #pragma unroll
        for (int mt = 0; mt < 2; mt++) ldsm4(af[mt], smu + a_off[mt] + ks * 32);
        #pragma unroll
        for (int np = 0; np < 4; np++) ldsm4(bf[np], smu + b_off[np] + ks * 32);
        #pragma unroll
        for (int mt = 0; mt < 2; mt++)
            #pragma unroll
            for (int nt = 0; nt < 8; nt++)
                mma16816(acc[mt][nt], af[mt], &bf[nt >> 1][(nt & 1) * 2]);
    }
    __syncthreads();

    int g = lane >> 2, tig = lane & 3;

    // epilogue: aenc tile (fp16) into stage region chunks 0..3
    #pragma unroll
    for (int mt = 0; mt < 2; mt++) {
        int row = wm * 32 + mt * 16 + g;
        #pragma unroll
        for (int nt = 0; nt < 8; nt++) {
            int col = wn * 64 + nt * 8 + 2 * tig;
            float b0 = aenc_b[a * 128 + col], b1 = aenc_b[a * 128 + col + 1];
            float v0 = lrelu(acc[mt][nt][0] + b0), v1 = lrelu(acc[mt][nt][1] + b1);
            float v2 = lrelu(acc[mt][nt][2] + b0), v3 = lrelu(acc[mt][nt][3] + b1);
            uint32_t tadr = (uint32_t)((col >> 5) * CHNK + row * PITCH + (col & 31) * 2);
            *(__half2*)(sm + tadr)             = __floats2half2_rn(v0, v1);
            *(__half2*)(sm + tadr + 8 * PITCH) = __floats2half2_rn(v2, v3);
            acc[mt][nt][0] = 0.f; acc[mt][nt][1] = 0.f;
            acc[mt][nt][2] = 0.f; acc[mt][nt][3] = 0.f;
        }
    }
    __syncthreads();

    auto cpB2 = [&](int c, int buf) {   // c 0..7: Wk chunks 0..3, Wv chunks 0..3
        const __half* src = (c < 4) ? Wkp : Wvp;
        int cc = c & 3;
        #pragma unroll
        for (int i = 0; i < 2; i++) {
            int s = tid + i * 256;
            int n = s >> 2, seg = s & 3;
            CP16(smu + BSOFF + buf * CHNK + n * PITCH + seg * 16,
                 src + (size_t)n * 128 + cc * 32 + seg * 8);
        }
    };

    // phase 2: stream Wk/Wv
    for (int c = 0; c < 8; c++) {
        int buf = c & 1;
        if (c + 1 < 8) { cpB2(c + 1, buf ^ 1); CPCOMMIT(); CPWAIT1(); }
        else           { CPWAIT0(); }
        __syncthreads();
        #pragma unroll
        for (int ks = 0; ks < 2; ks++) {
            uint32_t coffA = (uint32_t)((c & 3) * CHNK + ks * 32);
            uint32_t af[2][4], bf[4][4];
            #pragma unroll
            for (int mt = 0; mt < 2; mt++) ldsm4(af[mt], smu + a_off[mt] + coffA);
            #pragma unroll
            for (int np = 0; np < 4; np++) ldsm4(bf[np], smu + bs_off[np] + buf * CHNK + ks * 32);
            #pragma unroll
            for (int mt = 0; mt < 2; mt++)
                #pragma unroll
                for (int nt = 0; nt < 8; nt++)
                    mma16816(acc[mt][nt], af[mt], &bf[nt >> 1][(nt & 1) * 2]);
        }
        __syncthreads();

        if (c == 3 || c == 7) {
            bool isv = (c == 7);
            __half* outp = isv ? valsh : keysh;
            #pragma unroll
            for (int mt = 0; mt < 2; mt++) {
                int m = m0 + wm * 32 + mt * 16 + g;
                #pragma unroll
                for (int nt = 0; nt < 8; nt++) {
                    int col = wn * 64 + nt * 8 + 2 * tig;
                    float v0 = acc[mt][nt][0], v1 = acc[mt][nt][1];
                    float v2 = acc[mt][nt][2], v3 = acc[mt][nt][3];
                    if (isv) {
                        float b0 = valb[col], b1 = valb[col + 1];
                        v0 = lrelu(v0 + b0); v1 = lrelu(v1 + b1);
                        v2 = lrelu(v2 + b0); v3 = lrelu(v3 + b1);
                    }
                    *(__half2*)(outp + ((size_t)a * Bsz + m) * 128 + col) = __floats2half2_rn(v0, v1);
                    *(__half2*)(outp + ((size_t)a * Bsz + m + 8) * 128 + col) = __floats2half2_rn(v2, v3);
                    acc[mt][nt][0] = 0.f; acc[mt][nt][1] = 0.f;
                    acc[mt][nt][2] = 0.f; acc[mt][nt][3] = 0.f;
                }
            }
        }
    }
}

// ---------------- c1 + q fused, K=256 all fp16 ----------------
__global__ __launch_bounds__(256, 2) void c1q_k(
    const __half* __restrict__ sah, const __half* __restrict__ att,
    const __half* __restrict__ Bc1, const float* __restrict__ c1_b,
    const float* __restrict__ c2w, const float* __restrict__ c2b,
    float* __restrict__ qout) {

    __shared__ __align__(16) char sm[2][STAGE];
    uint32_t smu = smem_u32(sm);
    int tid = threadIdx.x, lane = tid & 31, wid = tid >> 5;
    int wm = wid & 3, wn = wid >> 2;
    int a = blockIdx.z, m0 = blockIdx.x * 128;

    const char* Ap  = (const char*)(sah + (size_t)a * Bsz * 128);
    const char* Atp = (const char*)(att + (size_t)a * Bsz * 128);
    const __half* Bp = Bc1 + (size_t)a * 128 * 256;

    auto cpA = [&](int c, int buf) {
        #pragma unroll
        for (int i = 0; i < 2; i++) {
            int p = tid + i * 256;
            int row = p >> 2, seg = p & 3;
            const char* g;
            if (c < 4) g = Ap + (size_t)(m0 + row) * 256 + c * 64 + seg * 16;
            else       g = Atp + (size_t)(m0 + row) * 256 + (c - 4) * 64 + seg * 16;
            CP16(smu + buf * STAGE + row * PITCH + seg * 16, g);
        }
    };
    auto cpB = [&](int c, int buf) {
        #pragma unroll
        for (int i = 0; i < 2; i++) {
            int s = tid + i * 256;
            int n = s >> 2, seg = s & 3;
            CP16(smu + buf * STAGE + CHNK + n * PITCH + seg * 16,
                 Bp + (size_t)n * 256 + c * 32 + seg * 8);
        }
    };

    int r = lane & 7, q = lane >> 3;
    uint32_t a_off[2], b_off[4];
    #pragma unroll
    for (int mt = 0; mt < 2; mt++)
        a_off[mt] = (uint32_t)((wm * 32 + mt * 16 + (q & 1) * 8 + r) * PITCH + (q >> 1) * 16);
    #pragma unroll
    for (int np = 0; np < 4; np++)
        b_off[np] = (uint32_t)(CHNK + (wn * 64 + np * 16 + (q >> 1) * 8 + r) * PITCH + (q & 1) * 16);

    float acc[2][8][4];
    #pragma unroll
    for (int mt = 0; mt < 2; mt++)
        #pragma unroll
        for (int nt = 0; nt < 8; nt++)
            #pragma unroll
            for (int i = 0; i < 4; i++) acc[mt][nt][i] = 0.f;

    cpA(0, 0); cpB(0, 0); CPCOMMIT();
    const int nch = 8;
    for (int c = 0; c < nch; c++) {
        int buf = c & 1;
        if (c + 1 < nch) { cpA(c + 1, buf ^ 1); cpB(c + 1, buf ^ 1); CPCOMMIT(); CPWAIT1(); }
        else             { CPWAIT0(); }
        __syncthreads();
        uint32_t bb = smu + buf * STAGE;
        #pragma unroll
        for (int ks = 0; ks < 2; ks++) {
            uint32_t af[2][4], bf[4][4];
            #pragma unroll
            for (int mt = 0; mt < 2; mt++) ldsm4(af[mt], bb + a_off[mt] + ks * 32);
            #pragma unroll
            for (int np = 0; np < 4; np++) ldsm4(bf[np], bb + b_off[np] + ks * 32);
            #pragma unroll
            for (int mt = 0; mt < 2; mt++)
                #pragma unroll
                for (int nt = 0; nt < 8; nt++)
                    mma16816(acc[mt][nt], af[mt], &bf[nt >> 1][(nt & 1) * 2]);
        }
        __syncthreads();
    }

    int g = lane >> 2, tig = lane & 3;
    float qp[4] = {0.f, 0.f, 0.f, 0.f};
    #pragma unroll
    for (int mt = 0; mt < 2; mt++)
        #pragma unroll
        for (int nt = 0; nt < 8; nt++) {
            int col = wn * 64 + nt * 8 + 2 * tig;
            float b0 = c1_b[a * 128 + col], b1 = c1_b[a * 128 + col + 1];
            float w0 = c2w[a * 128 + col], w1 = c2w[a * 128 + col + 1];
            qp[mt * 2]     += lrelu(acc[mt][nt][0] + b0) * w0 + lrelu(acc[mt][nt][1] + b1) * w1;
            qp[mt * 2 + 1] += lrelu(acc[mt][nt][2] + b0) * w0 + lrelu(acc[mt][nt][3] + b1) * w1;
        }
    #pragma unroll
    for (int j = 0; j < 4; j++) {
        qp[j] += __shfl_xor_sync(0xffffffffu, qp[j], 1);
        qp[j] += __shfl_xor_sync(0xffffffffu, qp[j], 2);
    }
    __syncthreads();
    float* qsm = (float*)sm;
    if (tig == 0) {
        #pragma unroll
        for (int j = 0; j < 4; j++) {
            int rl = wm * 32 + (j >> 1) * 16 + (j & 1) * 8 + g;
            qsm[rl * 2 + wn] = qp[j];
        }
    }
    __syncthreads();
    if (tid < 128)
        qout[(size_t)a * Bsz + m0 + tid] = qsm[tid * 2] + qsm[tid * 2 + 1] + c2b[a];
}

// ---------------- attention: 16 batch elts x 8 agents per block ----------
#define APITCH 36
__global__ __launch_bounds__(128) void attn_k() {
    __shared__ __half sS[128 * APITCH];
    __shared__ __half sK[128 * APITCH];
    int t = threadIdx.x;
    int b0 = blockIdx.x * 16;
    int bl = t >> 3, iq = t & 7;

    for (int kh = 0; kh < 4; kh++) {
        __syncthreads();
        {
            int lbl = t >> 3, ag = t & 7;
            size_t off = ((size_t)ag * Bsz + b0 + lbl) * 128 + kh * 32;
            const uint2* ps = (const uint2*)(g_selsh + off);
            const uint2* pk = (const uint2*)(g_keysh + off);
            uint2* ds = (uint2*)(sS + (lbl * 8 + ag) * APITCH);
            uint2* dk = (uint2*)(sK + (lbl * 8 + ag) * APITCH);
            #pragma unroll
            for (int j = 0; j < 8; j++) { ds[j] = ps[j]; dk[j] = pk[j]; }
        }
        __syncthreads();

        float sv[32];
        {
            const __half2* p = (const __half2*)(sS + (bl * 8 + iq) * APITCH);
            #pragma unroll
            for (int d = 0; d < 16; d++) {
                float2 f = __half22float2(p[d]);
                sv[2 * d] = f.x; sv[2 * d + 1] = f.y;
            }
        }
        float pj[8];
        #pragma unroll
        for (int j = 0; j < 8; j++) {
            const __half2* p = (const __half2*)(sK + (bl * 8 + j) * APITCH);
            float acc = 0.f;
            #pragma unroll
            for (int d = 0; d < 16; d++) {
                float2 f = __half22float2(p[d]);
                acc += sv[2 * d] * f.x + sv[2 * d + 1] * f.y;
            }
            pj[j] = acc * 0.17677669529663687f;
        }
        float mx = -1e30f;
        #pragma unroll
        for (int j = 0; j < 8; j++) if (j != iq) mx = fmaxf(mx, pj[j]);
        float sum = 0.f;
        #pragma unroll
        for (int j = 0; j < 8; j++) {
            pj[j] = (j == iq) ? 0.f : __expf(pj[j] - mx);
            sum += pj[j];
        }
        float inv = 1.f / sum;

        __syncthreads();
        {
            int lbl = t >> 3, ag = t & 7;
            size_t off = ((size_t)ag * Bsz + b0 + lbl) * 128 + kh * 32;
            const uint2* pv = (const uint2*)(g_valsh + off);
            uint2* ds = (uint2*)(sS + (lbl * 8 + ag) * APITCH);
            #pragma unroll
            for (int j = 0; j < 8; j++) ds[j] = pv[j];
        }
        __syncthreads();

        float ov[32];
        #pragma unroll
        for (int d = 0; d < 32; d++) ov[d] = 0.f;
        #pragma unroll
        for (int j = 0; j < 8; j++) {
            float w = pj[j] * inv;
            const __half2* p = (const __half2*)(sS + (bl * 8 + j) * APITCH);
            #pragma unroll
            for (int d = 0; d < 16; d++) {
                float2 f = __half22float2(p[d]);
                ov[2 * d]     += w * f.x;
                ov[2 * d + 1] += w * f.y;
            }
        }
        __half* dst = g_atth + ((size_t)iq * Bsz + b0 + bl) * 128 + kh * 32;
        #pragma unroll
        for (int d4 = 0; d4 < 4; d4++) {
            __half2 h0 = __floats2half2_rn(ov[d4 * 8 + 0], ov[d4 * 8 + 1]);
            __half2 h1 = __floats2half2_rn(ov[d4 * 8 + 2], ov[d4 * 8 + 3]);
            __half2 h2 = __floats2half2_rn(ov[d4 * 8 + 4], ov[d4 * 8 + 5]);
            __half2 h3 = __floats2half2_rn(ov[d4 * 8 + 6], ov[d4 * 8 + 7]);
            uint4 u;
            u.x = *(uint32_t*)&h0; u.y = *(uint32_t*)&h1;
            u.z = *(uint32_t*)&h2; u.w = *(uint32_t*)&h3;
            *(uint4*)(dst + d4 * 8) = u;
        }
    }
}

// ---------------- launch ----------------
extern "C" void kernel_launch(void* const* d_in, const int* in_sizes, int n_in,
                              void* d_out, int out_size) {
    const float* states = (const float*)d_in[0];
    const float* actions= (const float*)d_in[1];
    const float* enc_w  = (const float*)d_in[2];
    const float* enc_b  = (const float*)d_in[3];
    const float* aenc_w = (const float*)d_in[4];
    const float* aenc_b = (const float*)d_in[5];
    const float* key_w  = (const float*)d_in[6];
    const float* sel_w  = (const float*)d_in[7];
    const float* val_w  = (const float*)d_in[8];
    const float* val_b  = (const float*)d_in[9];
    const float* c1_w   = (const float*)d_in[10];
    const float* c1_b   = (const float*)d_in[11];
    const float* c2_w   = (const float*)d_in[12];
    const float* c2_b   = (const float*)d_in[13];
    float* out = (float*)d_out;

    void *p_sah, *p_keysh, *p_selsh, *p_valsh, *p_atth;
    void *p_Benc, *p_Baenc, *p_Bc1, *p_Wkp, *p_Wsp, *p_Wvp;
    cudaGetSymbolAddress(&p_sah,  g_sah);
    cudaGetSymbolAddress(&p_keysh,g_keysh);
    cudaGetSymbolAddress(&p_selsh,g_selsh);
    cudaGetSymbolAddress(&p_valsh,g_valsh);
    cudaGetSymbolAddress(&p_atth, g_atth);
    cudaGetSymbolAddress(&p_Benc, g_Benc);
    cudaGetSymbolAddress(&p_Baenc,g_Baenc);
    cudaGetSymbolAddress(&p_Bc1,  g_Bc1);
    cudaGetSymbolAddress(&p_Wkp,  g_Wkp);
    cudaGetSymbolAddress(&p_Wsp,  g_Wsp);
    cudaGetSymbolAddress(&p_Wvp,  g_Wvp);

    cudaFuncSetAttribute(sa_sels_k, cudaFuncAttributeMaxDynamicSharedMemorySize, 81920);
    cudaFuncSetAttribute(aenc_kv_k, cudaFuncAttributeMaxDynamicSharedMemorySize, 61440);

    bn_partial_k<<<dim3(32, 8), 320>>>(states, actions);
    bn_final_k<<<8, 160>>>();
    pack_w<<<dim3(10, 8), 256>>>(enc_w,  (__half*)p_Benc, 160, 0, 160, 0);
    pack_w<<<dim3(2, 8),  256>>>(aenc_w, (__half*)p_Baenc, 32, 0, 32, 0);
    pack_w<<<dim3(8, 8),  256>>>(c1_w,             (__half*)p_Bc1, 256, 0, 256, 0);
    pack_w<<<dim3(8, 8),  256>>>(c1_w + 128 * 128, (__half*)p_Bc1, 256, 0, 256, 128);
    pack_w<<<dim3(8, 1),  256>>>(key_w,  (__half*)p_Wkp, 128, 1, 128, 0);
    pack_w<<<dim3(8, 1),  256>>>(sel_w,  (__half*)p_Wsp, 128, 1, 128, 0);
    pack_w<<<dim3(8, 1),  256>>>(val_w,  (__half*)p_Wvp, 128, 1, 128, 0);

    dim3 gg(256, 1, 8);
    sa_sels_k<<<gg, 256, 81920>>>(states, actions,
                                  (const __half*)p_Benc, enc_b,
                                  (const __half*)p_Wsp,
                                  (__half*)p_sah, (__half*)p_selsh);
    aenc_kv_k<<<gg, 256, 61440>>>(actions,
                                  (const __half*)p_Baenc, aenc_b,
                                  (const __half*)p_Wkp, (const __half*)p_Wvp,
                                  val_b, (__half*)p_keysh, (__half*)p_valsh);
    attn_k<<<Bsz / 16, 128>>>();
    c1q_k<<<gg, 256>>>((const __half*)p_sah, (const __half*)p_atth,
                       (const __half*)p_Bc1, c1_b, c2_w, c2_b, out);
}